// round 10
// baseline (speedup 1.0000x reference)
#include <cuda_runtime.h>
#include <cuda_bf16.h>
#include <math.h>
#include <stdint.h>

#define BN 8192
#define DD 256
#define SS 32

// ---------------- device scratch ----------------
__device__ __nv_bfloat16 g_znb[BN * DD]; // normalized z, bf16
__device__ __nv_bfloat16 g_bh[BN * SS];  // binding rows, bf16 (hi)
__device__ float g_cexp[BN];    // exp(-2*||zn_i||^2)
__device__ float g_sdiag[BN];   // ||zn_i||^2 fp32 (exact diagonal sim)
__device__ float g_bsq[BN];     // ||binding_i||^2
__device__ float g_denom[BN];   // per-row sum exp(sim/tau)
__device__ float g_possim[BN];  // sim[i, pos[i]]
__device__ float g_unif;        // sum over all pairs exp(-2*d2)
__device__ int   g_p8i[BN * 32]; // per-(query,nsplit) approx top-8 indices

__device__ __forceinline__ float warpsum(float v) {
#pragma unroll
    for (int o = 16; o > 0; o >>= 1) v += __shfl_down_sync(0xffffffffu, v, o);
    return v;
}
__device__ __forceinline__ uint32_t smem_u32(const void* p) {
    uint32_t a;
    asm("{ .reg .u64 t; cvta.to.shared.u64 t, %1; cvt.u32.u64 %0, t; }" : "=r"(a) : "l"(p));
    return a;
}
__device__ __forceinline__ void ldsm4(uint32_t& r0, uint32_t& r1, uint32_t& r2, uint32_t& r3, uint32_t a) {
    asm volatile("ldmatrix.sync.aligned.m8n8.x4.shared.b16 {%0,%1,%2,%3}, [%4];"
                 : "=r"(r0), "=r"(r1), "=r"(r2), "=r"(r3) : "r"(a));
}
__device__ __forceinline__ void hmma(float* c, const uint32_t* a, const uint32_t* b) {
    asm volatile(
        "mma.sync.aligned.m16n8k16.row.col.f32.bf16.bf16.f32 "
        "{%0,%1,%2,%3}, {%4,%5,%6,%7}, {%8,%9}, {%0,%1,%2,%3};"
        : "+f"(c[0]), "+f"(c[1]), "+f"(c[2]), "+f"(c[3])
        : "r"(a[0]), "r"(a[1]), "r"(a[2]), "r"(a[3]), "r"(b[0]), "r"(b[1]));
}
__device__ __forceinline__ void cpasync16(uint32_t dst, const void* src) {
    asm volatile("cp.async.ca.shared.global [%0], [%1], 16;"
                 :: "r"(dst), "l"(__cvta_generic_to_global(src)) : "memory");
}
#define CP_COMMIT() asm volatile("cp.async.commit_group;" ::: "memory")
#define CP_WAIT1()  asm volatile("cp.async.wait_group 1;" ::: "memory")
#define CP_WAIT0()  asm volatile("cp.async.wait_group 0;" ::: "memory")

// sorted-5 insert, strict < keeps lowest-index-first on ties
__device__ __forceinline__ void ins5(float sc, int j, float* s, int* id) {
    if (sc < s[4]) {
        if (sc < s[2]) {
            s[4] = s[3]; id[4] = id[3]; s[3] = s[2]; id[3] = id[2];
            if (sc < s[1]) {
                s[2] = s[1]; id[2] = id[1];
                if (sc < s[0]) { s[1] = s[0]; id[1] = id[0]; s[0] = sc; id[0] = j; }
                else           { s[1] = sc; id[1] = j; }
            } else             { s[2] = sc; id[2] = j; }
        } else {
            if (sc < s[3]) { s[4] = s[3]; id[4] = id[3]; s[3] = sc; id[3] = j; }
            else           { s[4] = sc; id[4] = j; }
        }
    }
}

// ---------------- threefry2x32 (exact JAX, partitionable) ----------------
__device__ __forceinline__ void tf2x32(unsigned k0, unsigned k1,
                                       unsigned x0, unsigned x1,
                                       unsigned& o0, unsigned& o1) {
    unsigned ks0 = k0, ks1 = k1, ks2 = k0 ^ k1 ^ 0x1BD11BDAu;
    x0 += ks0; x1 += ks1;
#define TFR(r) { x0 += x1; x1 = (x1 << r) | (x1 >> (32 - r)); x1 ^= x0; }
    TFR(13) TFR(15) TFR(26) TFR(6)   x0 += ks1; x1 += ks2 + 1u;
    TFR(17) TFR(29) TFR(16) TFR(24)  x0 += ks2; x1 += ks0 + 2u;
    TFR(13) TFR(15) TFR(26) TFR(6)   x0 += ks0; x1 += ks1 + 3u;
    TFR(17) TFR(29) TFR(16) TFR(24)  x0 += ks1; x1 += ks2 + 4u;
    TFR(13) TFR(15) TFR(26) TFR(6)   x0 += ks2; x1 += ks0 + 5u;
#undef TFR
    o0 = x0; o1 = x1;
}
__device__ __forceinline__ int jax_choice5(unsigned i) {
    unsigned a, b, k1a, k1b, k2a, k2b;
    tf2x32(0u, 42u, 0u, 0u, k1a, k1b);
    tf2x32(0u, 42u, 0u, 1u, k2a, k2b);
    tf2x32(k1a, k1b, 0u, i, a, b); unsigned h = a ^ b;
    tf2x32(k2a, k2b, 0u, i, a, b); unsigned l = a ^ b;
    return (int)(((h % 5u) + (l % 5u)) % 5u);
}

// ---------------- kernel A: normalize -> bf16, norms, packs -----------------
__global__ void kA(const float* __restrict__ z, const float* __restrict__ bs) {
    int w = threadIdx.x >> 5, lane = threadIdx.x & 31;
    int r = blockIdx.x * 8 + w;
    const float4* zr = (const float4*)(z + (size_t)r * DD);
    float4 a = zr[2 * lane];
    float4 b = zr[2 * lane + 1];
    float ss = a.x*a.x + a.y*a.y + a.z*a.z + a.w*a.w
             + b.x*b.x + b.y*b.y + b.z*b.z + b.w*b.w;
    ss = warpsum(ss);
    ss = __shfl_sync(0xffffffffu, ss, 0);
    float inv = 1.0f / sqrtf(ss);
    __nv_bfloat162 pk[4];
    pk[0] = __floats2bfloat162_rn(a.x * inv, a.y * inv);
    pk[1] = __floats2bfloat162_rn(a.z * inv, a.w * inv);
    pk[2] = __floats2bfloat162_rn(b.x * inv, b.y * inv);
    pk[3] = __floats2bfloat162_rn(b.z * inv, b.w * inv);
    ((uint4*)(g_znb + (size_t)r * DD))[lane] = *(uint4*)pk;

    float bv = bs[(size_t)r * SS + lane];
    g_bh[r * SS + lane] = __float2bfloat16_rn(bv);
    float bq = warpsum(bv * bv);
    if (lane == 0) {
        float s2 = ss * inv * inv;
        g_cexp[r] = __expf(-2.0f * s2);
        g_sdiag[r] = s2;
        g_bsq[r] = bq;
        g_denom[r] = 0.0f;
    }
    if (blockIdx.x == 0 && threadIdx.x == 0) g_unif = 0.0f;
}

// ---------------- kernel Bg: approx (hi-only) top-8 per split ---------------
#define BG_A     0
#define BG_S(s)  (16384 + (s) * 16896)
#define BG_BSQ(s) (BG_S(s) + 16384)
#define BG_MS    0
#define BG_MI    16384
#define KB_SMEM  (16384 + 2 * 16896)

__device__ __forceinline__ void bg_load(int chunk, int stage, int ns, uint32_t sb, int tid) {
    int j0 = ns * 2048 + chunk * 128;
    for (int f = tid; f < 544; f += 256) {
        if (f < 512) {
            int row = f >> 2, u = f & 3;
            cpasync16(sb + BG_S(stage) + row * 128 + (((u) ^ (row & 7)) << 4),
                      g_bh + (size_t)(j0 + row) * SS + u * 8);
        } else {
            int i = f - 512;
            cpasync16(sb + BG_BSQ(stage) + i * 16, g_bsq + j0 + i * 4);
        }
    }
}

__global__ void __launch_bounds__(256, 2) kBg() {
    extern __shared__ char smem[];
    const int qb = blockIdx.x, ns = blockIdx.y;
    const int tid = threadIdx.x, wid = tid >> 5, lane = tid & 31;
    const uint32_t sb = smem_u32(smem);

    for (int f = tid; f < 512; f += 256) {
        int row = f >> 2, u = f & 3;
        uint4 v = ((const uint4*)g_bh)[(size_t)(qb * 128 + row) * 4 + u];
        *(uint4*)(smem + BG_A + row * 128 + (((u) ^ (row & 7)) << 4)) = v;
    }
    bg_load(0, 0, ns, sb, tid); CP_COMMIT();
    bg_load(1, 1, ns, sb, tid); CP_COMMIT();
    __syncthreads();

    const int rA = lane & 15, chA = lane >> 4;
    const int arow = wid * 16 + rA;
    uint32_t af[2][4];
#pragma unroll
    for (int ks = 0; ks < 2; ks++)
        ldsm4(af[ks][0], af[ks][1], af[ks][2], af[ks][3],
              sb + BG_A + arow * 128 + (((2 * ks + chA) ^ (arow & 7)) << 4));

    const int qrow = lane >> 2, qcol = lane & 3;
    const int qg0 = qb * 128 + wid * 16 + qrow;
    const int qg1 = qg0 + 8;
    const float INF = __int_as_float(0x7f800000);
    float ts0[5], ts1[5]; int ti0[5], ti1[5];
#pragma unroll
    for (int k = 0; k < 5; k++) {
        ts0[k] = INF; ts1[k] = INF; ti0[k] = 0x7fffffff; ti1[k] = 0x7fffffff;
    }
    const int rB = ((lane >> 4) << 3) + (lane & 7), chB = (lane >> 3) & 1;

    for (int it = 0; it < 16; it++) {
        CP_WAIT1();
        __syncthreads();
        int st = it & 1;
        uint32_t SB = sb + BG_S(st);
        const float* sbq = (const float*)(smem + BG_BSQ(st));
        int j0 = ns * 2048 + it * 128;
#pragma unroll
        for (int p = 0; p < 8; p++) {
            int brow = p * 16 + rB;
            uint32_t ba = SB + brow * 128;
            int bx = brow & 7;
            uint32_t b0[4], b1[4];
            ldsm4(b0[0], b0[1], b0[2], b0[3], ba + (((0 + chB) ^ bx) << 4));
            ldsm4(b1[0], b1[1], b1[2], b1[3], ba + (((2 + chB) ^ bx) << 4));
            float acc[2][4] = {};
            hmma(acc[0], af[0], &b0[0]);
            hmma(acc[1], af[0], &b0[2]);
            hmma(acc[0], af[1], &b1[0]);
            hmma(acc[1], af[1], &b1[2]);
            // 4 candidate scores per row; quad-min fast path, rare slow insert
            float scr0[4], scr1[4];
#pragma unroll
            for (int n2 = 0; n2 < 2; n2++) {
#pragma unroll
                for (int e = 0; e < 2; e++) {
                    int idx = n2 * 2 + e;
                    float bq = sbq[p * 16 + n2 * 8 + qcol * 2 + e];
                    scr0[idx] = fmaf(-2.0f, acc[n2][e], bq);
                    scr1[idx] = fmaf(-2.0f, acc[n2][2 + e], bq);
                }
            }
            float m0 = fminf(fminf(scr0[0], scr0[1]), fminf(scr0[2], scr0[3]));
            float m1 = fminf(fminf(scr1[0], scr1[1]), fminf(scr1[2], scr1[3]));
            if (m0 < ts0[4]) {
#pragma unroll
                for (int idx = 0; idx < 4; idx++) {
                    int j = j0 + p * 16 + (idx >> 1) * 8 + qcol * 2 + (idx & 1);
                    if (j != qg0) ins5(scr0[idx], j, ts0, ti0);
                }
            }
            if (m1 < ts1[4]) {
#pragma unroll
                for (int idx = 0; idx < 4; idx++) {
                    int j = j0 + p * 16 + (idx >> 1) * 8 + qcol * 2 + (idx & 1);
                    if (j != qg1) ins5(scr1[idx], j, ts1, ti1);
                }
            }
        }
        __syncthreads();
        if (it < 14) bg_load(it + 2, it & 1, ns, sb, tid);
        CP_COMMIT();
    }
    CP_WAIT0();
    __syncthreads();

    float* ms = (float*)(smem + BG_MS);
    int*   mi = (int*)(smem + BG_MI);
    {
        int r0 = wid * 16 + qrow, r1 = r0 + 8;
#pragma unroll
        for (int k = 0; k < 5; k++) {
            ms[(r0 * 4 + qcol) * 5 + k] = ts0[k]; mi[(r0 * 4 + qcol) * 5 + k] = ti0[k];
            ms[(r1 * 4 + qcol) * 5 + k] = ts1[k]; mi[(r1 * 4 + qcol) * 5 + k] = ti1[k];
        }
    }
    __syncthreads();
    if (tid < 128) {
        int p4[4] = {0, 0, 0, 0};
        int q = qb * 128 + tid;
#pragma unroll
        for (int slot = 0; slot < 8; slot++) {
            float bsc = INF; int bidx = 0x7fffffff, bg = 0;
#pragma unroll
            for (int g = 0; g < 4; g++) {
                if (p4[g] < 5) {
                    float s = ms[(tid * 4 + g) * 5 + p4[g]];
                    int i = mi[(tid * 4 + g) * 5 + p4[g]];
                    if (s < bsc || (s == bsc && i < bidx)) { bsc = s; bidx = i; bg = g; }
                }
            }
            g_p8i[q * 32 + ns * 8 + slot] = bidx;
            p4[bg]++;
        }
    }
}

// ---------------- kernel B3D: exact rescore + choice + pos_sim --------------
__global__ void kB3D(const float* __restrict__ bs) {
    __shared__ float qr[8][32];
    int tid = threadIdx.x, wid = tid >> 5, lane = tid & 31;
    int q = blockIdx.x * 8 + wid;
    qr[wid][lane] = bs[(size_t)q * SS + lane];
    __syncwarp();
    int j = g_p8i[q * 32 + lane];
    const float4* cp4 = (const float4*)(bs + (size_t)j * SS);
    const float4* qp4 = (const float4*)qr[wid];
    float dot = 0.0f;
#pragma unroll
    for (int k = 0; k < 8; k++) {
        float4 cv = cp4[k], qv = qp4[k];
        dot += qv.x * cv.x + qv.y * cv.y + qv.z * cv.z + qv.w * cv.w;
    }
    float s = g_bsq[j] - 2.0f * dot;
    int id = j;
    const float INF = __int_as_float(0x7f800000);
    int c = jax_choice5((unsigned)q);
    int chosen = 0;
#pragma unroll
    for (int slot = 0; slot < 5; slot++) {
        float msv = s; int miv = id;
#pragma unroll
        for (int o = 16; o > 0; o >>= 1) {
            float os = __shfl_xor_sync(0xffffffffu, msv, o);
            int oi = __shfl_xor_sync(0xffffffffu, miv, o);
            if (os < msv || (os == msv && oi < miv)) { msv = os; miv = oi; }
        }
        if (slot == c) chosen = miv;
        if (id == miv) s = INF;
    }
    chosen = __shfl_sync(0xffffffffu, chosen, 0);
    // pos_sim: zn[q] . zn[chosen] in bf16
    uint4 ur = ((const uint4*)(g_znb + (size_t)q * DD))[lane];
    uint4 up = ((const uint4*)(g_znb + (size_t)chosen * DD))[lane];
    const __nv_bfloat162* br = (const __nv_bfloat162*)&ur;
    const __nv_bfloat162* bp = (const __nv_bfloat162*)&up;
    float acc = 0.0f;
#pragma unroll
    for (int e = 0; e < 4; e++) {
        float2 fr = __bfloat1622float2(br[e]);
        float2 fp = __bfloat1622float2(bp[e]);
        acc += fr.x * fp.x + fr.y * fp.y;
    }
    acc = warpsum(acc);
    if (lane == 0) g_possim[q] = acc;
}

// ---------------- kernel C: 128x256 super-tile HMMA + fused epilogue --------
// 1056 blocks x 512 thr (4x4 warps, 32x32 warp tiles per 128-col half).
// A tile (128 rows, full K=256) resident; B streamed in 64-K chunks, 2-stage.
#define KC_A    0
#define KC_BS(s) (65536 + (s) * 16384)
#define KC_CA   98304
#define KC_CB   98816
#define KC_SD   99328
#define KC_RS   99840
#define KC_CS   100352
#define KC_RED  100864
#define KC_SMEM 100992

__device__ __forceinline__ void kc_loadA(int bi, uint32_t sb, int tid) {
#pragma unroll
    for (int i = 0; i < 8; i++) {
        int f = tid + i * 512;
        int row = f >> 5, u = f & 31;
        cpasync16(sb + KC_A + row * 512 + (((u) ^ (row & 7)) << 4),
                  g_znb + (size_t)(bi * 128 + row) * DD + u * 8);
    }
}
__device__ __forceinline__ void kc_loadB(int bjj, int kc, int stage, uint32_t sb, int tid) {
#pragma unroll
    for (int i = 0; i < 2; i++) {
        int f = tid + i * 512;
        int row = f >> 3, u = f & 7;
        cpasync16(sb + KC_BS(stage) + row * 128 + (((u) ^ (row & 7)) << 4),
                  g_znb + (size_t)(bjj * 128 + row) * DD + kc * 64 + u * 8);
    }
}

__global__ void __launch_bounds__(512, 1) kC() {
    extern __shared__ char smem[];
    const int tid = threadIdx.x, wid = tid >> 5, lane = tid & 31;
    const int warp_m = wid >> 2, warp_n = wid & 3;
    const uint32_t sb = smem_u32(smem);

    // map blockIdx.x -> (bi, cblk), cblk in [bi/2, 32)
    int t = blockIdx.x, bi = 0;
    for (;;) { int cnt = 32 - (bi >> 1); if (t < cnt) break; t -= cnt; bi++; }
    const int cblk = (bi >> 1) + t;

    float* ca = (float*)(smem + KC_CA);
    float* cb = (float*)(smem + KC_CB);
    float* sdg = (float*)(smem + KC_SD);
    float* rsum = (float*)(smem + KC_RS);
    float* csum = (float*)(smem + KC_CS);
    float* red = (float*)(smem + KC_RED);

    kc_loadA(bi, sb, tid); CP_COMMIT();
    kc_loadB(2 * cblk, 0, 0, sb, tid); CP_COMMIT();
    kc_loadB(2 * cblk, 1, 1, sb, tid); CP_COMMIT();

    if (tid < 128) {
        ca[tid] = g_cexp[bi * 128 + tid];
        sdg[tid] = g_sdiag[bi * 128 + tid];
    }

    const int rA = lane & 15, chA = lane >> 4;
    const int rB = ((lane >> 4) << 3) + (lane & 7), chB = (lane >> 3) & 1;
    uint32_t aoff[2], boff[2];
    int ax[2], bx[2];
#pragma unroll
    for (int mi = 0; mi < 2; mi++) {
        int row = warp_m * 32 + mi * 16 + rA;
        aoff[mi] = row * 512; ax[mi] = row & 7;
    }
#pragma unroll
    for (int nb = 0; nb < 2; nb++) {
        int row = warp_n * 32 + nb * 16 + rB;
        boff[nb] = row * 128; bx[nb] = row & 7;
    }
    const int qrow = lane >> 2, qcol = (lane & 3) * 2;

#pragma unroll 1
    for (int h = 0; h < 2; h++) {
        const int bjj = 2 * cblk + h;
        float acc[2][4][4] = {};
#pragma unroll
        for (int kc = 0; kc < 4; kc++) {
            CP_WAIT1();
            __syncthreads();
            uint32_t SA = sb + KC_A, SB = sb + KC_BS(kc & 1);
#pragma unroll
            for (int ks = 0; ks < 4; ks++) {
                uint32_t af[2][4], bf[2][4];
#pragma unroll
                for (int mi = 0; mi < 2; mi++) {
                    int c = 2 * (kc * 4 + ks) + chA;
                    ldsm4(af[mi][0], af[mi][1], af[mi][2], af[mi][3],
                          SA + aoff[mi] + ((c ^ ax[mi]) << 4));
                }
#pragma unroll
                for (int nb = 0; nb < 2; nb++) {
                    int c = 2 * ks + chB;
                    ldsm4(bf[nb][0], bf[nb][1], bf[nb][2], bf[nb][3],
                          SB + boff[nb] + ((c ^ bx[nb]) << 4));
                }
#pragma unroll
                for (int mi = 0; mi < 2; mi++)
#pragma unroll
                    for (int ni = 0; ni < 4; ni++)
                        hmma(acc[mi][ni], af[mi], &bf[ni >> 1][(ni & 1) * 2]);
            }
            __syncthreads();
            int p = h * 4 + kc + 2;
            if (p < 8) kc_loadB(2 * cblk + (p >> 2), p & 3, kc & 1, sb, tid);
            CP_COMMIT();
        }

        if (bjj < bi) continue;  // duplicate (below diagonal) half: skip epilogue
        const bool diag = (bjj == bi);
        __syncthreads();
        if (tid < 128) {
            rsum[tid] = 0.0f; csum[tid] = 0.0f;
            cb[tid] = g_cexp[bjj * 128 + tid];
        }
        __syncthreads();

        float usum = 0.0f;
        float rowacc[2][2] = {};
        float colacc[4][2] = {};
#pragma unroll
        for (int mi = 0; mi < 2; mi++) {
#pragma unroll
            for (int hh = 0; hh < 2; hh++) {
                int lr = warp_m * 32 + mi * 16 + hh * 8 + qrow;
                float cav = ca[lr];
                float sdv = sdg[lr];
#pragma unroll
                for (int ni = 0; ni < 4; ni++) {
#pragma unroll
                    for (int e = 0; e < 2; e++) {
                        int lc = warp_n * 32 + ni * 8 + qcol + e;
                        float s = acc[mi][ni][hh * 2 + e];
                        if (diag && lc == lr) s = sdv;
                        float e2 = __expf(2.0f * s);
                        float e4 = e2 * e2;
                        float e10 = e4 * e4 * e2;
                        rowacc[mi][hh] += e10;
                        colacc[ni][e] += e10;
                        usum += fminf(cav * cb[lc] * e4, 1.0f);
                    }
                }
            }
        }
#pragma unroll
        for (int mi = 0; mi < 2; mi++)
#pragma unroll
            for (int hh = 0; hh < 2; hh++) {
                float v = rowacc[mi][hh];
                v += __shfl_xor_sync(0xffffffffu, v, 1);
                v += __shfl_xor_sync(0xffffffffu, v, 2);
                if ((lane & 3) == 0)
                    atomicAdd(&rsum[warp_m * 32 + mi * 16 + hh * 8 + qrow], v);
            }
#pragma unroll
        for (int ni = 0; ni < 4; ni++)
#pragma unroll
            for (int e = 0; e < 2; e++) {
                float v = colacc[ni][e];
                v += __shfl_xor_sync(0xffffffffu, v, 4);
                v += __shfl_xor_sync(0xffffffffu, v, 8);
                v += __shfl_xor_sync(0xffffffffu, v, 16);
                if (lane < 4)
                    atomicAdd(&csum[warp_n * 32 + ni * 8 + qcol + e], v);
            }
        usum = warpsum(usum);
        if (lane == 0) red[wid] = usum;
        __syncthreads();
        if (tid == 0) {
            float tt = 0.0f;
#pragma unroll
            for (int w = 0; w < 16; w++) tt += red[w];
            atomicAdd(&g_unif, diag ? tt : 2.0f * tt);
        }
        if (tid < 128) {
            atomicAdd(&g_denom[bi * 128 + tid], rsum[tid]);
            if (!diag) atomicAdd(&g_denom[bjj * 128 + tid], csum[tid]);
        }
    }
}

// ---------------- kernel E: final scalar (1024 thr, fast log) ---------------
__global__ void kE(float* __restrict__ out) {
    __shared__ float red[1024];
    int tid = threadIdx.x;
    float acc = 0.0f;
#pragma unroll
    for (int i = tid; i < BN; i += 1024)
        acc += __logf(g_denom[i] + 1e-8f) - g_possim[i] * 10.0f;
    red[tid] = acc;
    __syncthreads();
#pragma unroll
    for (int o = 512; o > 0; o >>= 1) {
        if (tid < o) red[tid] += red[tid + o];
        __syncthreads();
    }
    if (tid == 0) {
        float linfo = red[0] / 8192.0f;
        float lunif = __logf(g_unif * (1.0f / (8192.0f * 8192.0f)) + 1e-8f);
        out[0] = linfo + 0.1f * lunif;
    }
}

extern "C" void kernel_launch(void* const* d_in, const int* in_sizes, int n_in,
                              void* d_out, int out_size) {
    const float* z  = (const float*)d_in[0];
    const float* bs = (const float*)d_in[1];
    float* out = (float*)d_out;
    cudaFuncSetAttribute(kBg, cudaFuncAttributeMaxDynamicSharedMemorySize, KB_SMEM);
    cudaFuncSetAttribute(kC, cudaFuncAttributeMaxDynamicSharedMemorySize, KC_SMEM);

    // fork-join: binding chain (kBg->kB3D) runs concurrently with kC.
    cudaStream_t s1;
    cudaEvent_t eF, eJ;
    cudaStreamCreateWithFlags(&s1, cudaStreamNonBlocking);
    cudaEventCreateWithFlags(&eF, cudaEventDisableTiming);
    cudaEventCreateWithFlags(&eJ, cudaEventDisableTiming);

    kA<<<1024, 256>>>(z, bs);
    cudaEventRecord(eF, 0);
    cudaStreamWaitEvent(s1, eF, 0);

    kBg<<<dim3(64, 4), 256, KB_SMEM, s1>>>();
    kB3D<<<1024, 256, 0, s1>>>(bs);
    cudaEventRecord(eJ, s1);

    kC<<<1056, 512, KC_SMEM>>>();

    cudaStreamWaitEvent(0, eJ, 0);
    kE<<<1, 1024>>>(out);
    // streams/events intentionally not destroyed (capture-involved objects).
}

// round 11
// speedup vs baseline: 1.0664x; 1.0664x over previous
#include <cuda_runtime.h>
#include <cuda_bf16.h>
#include <math.h>
#include <stdint.h>

#define BN 8192
#define DD 256
#define SS 32

// ---------------- device scratch ----------------
__device__ __nv_bfloat16 g_znb[BN * DD]; // normalized z, bf16
__device__ __nv_bfloat16 g_bh[BN * SS];  // binding rows, bf16 (hi)
__device__ float g_cexp[BN];    // exp(-2*||zn_i||^2)
__device__ float g_sdiag[BN];   // ||zn_i||^2 fp32 (exact diagonal sim)
__device__ float g_bsq[BN];     // ||binding_i||^2
__device__ float g_denom[BN];   // per-row sum exp(sim/tau)
__device__ float g_possim[BN];  // sim[i, pos[i]]
__device__ float g_unif;        // sum over all pairs exp(-2*d2)
__device__ int   g_p8i[BN * 32]; // per-(query,nsplit) approx top-8 indices

__device__ __forceinline__ float warpsum(float v) {
#pragma unroll
    for (int o = 16; o > 0; o >>= 1) v += __shfl_down_sync(0xffffffffu, v, o);
    return v;
}
__device__ __forceinline__ uint32_t smem_u32(const void* p) {
    uint32_t a;
    asm("{ .reg .u64 t; cvta.to.shared.u64 t, %1; cvt.u32.u64 %0, t; }" : "=r"(a) : "l"(p));
    return a;
}
__device__ __forceinline__ void ldsm4(uint32_t& r0, uint32_t& r1, uint32_t& r2, uint32_t& r3, uint32_t a) {
    asm volatile("ldmatrix.sync.aligned.m8n8.x4.shared.b16 {%0,%1,%2,%3}, [%4];"
                 : "=r"(r0), "=r"(r1), "=r"(r2), "=r"(r3) : "r"(a));
}
__device__ __forceinline__ void hmma(float* c, const uint32_t* a, const uint32_t* b) {
    asm volatile(
        "mma.sync.aligned.m16n8k16.row.col.f32.bf16.bf16.f32 "
        "{%0,%1,%2,%3}, {%4,%5,%6,%7}, {%8,%9}, {%0,%1,%2,%3};"
        : "+f"(c[0]), "+f"(c[1]), "+f"(c[2]), "+f"(c[3])
        : "r"(a[0]), "r"(a[1]), "r"(a[2]), "r"(a[3]), "r"(b[0]), "r"(b[1]));
}
__device__ __forceinline__ void cpasync16(uint32_t dst, const void* src) {
    asm volatile("cp.async.ca.shared.global [%0], [%1], 16;"
                 :: "r"(dst), "l"(__cvta_generic_to_global(src)) : "memory");
}
#define CP_COMMIT() asm volatile("cp.async.commit_group;" ::: "memory")
#define CP_WAIT1()  asm volatile("cp.async.wait_group 1;" ::: "memory")
#define CP_WAIT0()  asm volatile("cp.async.wait_group 0;" ::: "memory")

// sorted-5 insert, strict < keeps lowest-index-first on ties
__device__ __forceinline__ void ins5(float sc, int j, float* s, int* id) {
    if (sc < s[4]) {
        if (sc < s[2]) {
            s[4] = s[3]; id[4] = id[3]; s[3] = s[2]; id[3] = id[2];
            if (sc < s[1]) {
                s[2] = s[1]; id[2] = id[1];
                if (sc < s[0]) { s[1] = s[0]; id[1] = id[0]; s[0] = sc; id[0] = j; }
                else           { s[1] = sc; id[1] = j; }
            } else             { s[2] = sc; id[2] = j; }
        } else {
            if (sc < s[3]) { s[4] = s[3]; id[4] = id[3]; s[3] = sc; id[3] = j; }
            else           { s[4] = sc; id[4] = j; }
        }
    }
}

// ---------------- threefry2x32 (exact JAX, partitionable) ----------------
__device__ __forceinline__ void tf2x32(unsigned k0, unsigned k1,
                                       unsigned x0, unsigned x1,
                                       unsigned& o0, unsigned& o1) {
    unsigned ks0 = k0, ks1 = k1, ks2 = k0 ^ k1 ^ 0x1BD11BDAu;
    x0 += ks0; x1 += ks1;
#define TFR(r) { x0 += x1; x1 = (x1 << r) | (x1 >> (32 - r)); x1 ^= x0; }
    TFR(13) TFR(15) TFR(26) TFR(6)   x0 += ks1; x1 += ks2 + 1u;
    TFR(17) TFR(29) TFR(16) TFR(24)  x0 += ks2; x1 += ks0 + 2u;
    TFR(13) TFR(15) TFR(26) TFR(6)   x0 += ks0; x1 += ks1 + 3u;
    TFR(17) TFR(29) TFR(16) TFR(24)  x0 += ks1; x1 += ks2 + 4u;
    TFR(13) TFR(15) TFR(26) TFR(6)   x0 += ks2; x1 += ks0 + 5u;
#undef TFR
    o0 = x0; o1 = x1;
}
__device__ __forceinline__ int jax_choice5(unsigned i) {
    unsigned a, b, k1a, k1b, k2a, k2b;
    tf2x32(0u, 42u, 0u, 0u, k1a, k1b);
    tf2x32(0u, 42u, 0u, 1u, k2a, k2b);
    tf2x32(k1a, k1b, 0u, i, a, b); unsigned h = a ^ b;
    tf2x32(k2a, k2b, 0u, i, a, b); unsigned l = a ^ b;
    return (int)(((h % 5u) + (l % 5u)) % 5u);
}

// ---------------- kernel A: normalize -> bf16, norms, packs -----------------
__global__ void kA(const float* __restrict__ z, const float* __restrict__ bs) {
    int w = threadIdx.x >> 5, lane = threadIdx.x & 31;
    int r = blockIdx.x * 8 + w;
    const float4* zr = (const float4*)(z + (size_t)r * DD);
    float4 a = zr[2 * lane];
    float4 b = zr[2 * lane + 1];
    float ss = a.x*a.x + a.y*a.y + a.z*a.z + a.w*a.w
             + b.x*b.x + b.y*b.y + b.z*b.z + b.w*b.w;
    ss = warpsum(ss);
    ss = __shfl_sync(0xffffffffu, ss, 0);
    float inv = 1.0f / sqrtf(ss);
    __nv_bfloat162 pk[4];
    pk[0] = __floats2bfloat162_rn(a.x * inv, a.y * inv);
    pk[1] = __floats2bfloat162_rn(a.z * inv, a.w * inv);
    pk[2] = __floats2bfloat162_rn(b.x * inv, b.y * inv);
    pk[3] = __floats2bfloat162_rn(b.z * inv, b.w * inv);
    ((uint4*)(g_znb + (size_t)r * DD))[lane] = *(uint4*)pk;

    float bv = bs[(size_t)r * SS + lane];
    g_bh[r * SS + lane] = __float2bfloat16_rn(bv);
    float bq = warpsum(bv * bv);
    if (lane == 0) {
        float s2 = ss * inv * inv;
        g_cexp[r] = __expf(-2.0f * s2);
        g_sdiag[r] = s2;
        g_bsq[r] = bq;
        g_denom[r] = 0.0f;
    }
    if (blockIdx.x == 0 && threadIdx.x == 0) g_unif = 0.0f;
}

// ---------------- kernel Bg: approx (hi-only) top-8 per split ---------------
#define BG_A     0
#define BG_S(s)  (16384 + (s) * 16896)
#define BG_BSQ(s) (BG_S(s) + 16384)
#define BG_MS    0
#define BG_MI    16384
#define KB_SMEM  (16384 + 2 * 16896)

__device__ __forceinline__ void bg_load(int chunk, int stage, int ns, uint32_t sb, int tid) {
    int j0 = ns * 2048 + chunk * 128;
    for (int f = tid; f < 544; f += 256) {
        if (f < 512) {
            int row = f >> 2, u = f & 3;
            cpasync16(sb + BG_S(stage) + row * 128 + (((u) ^ (row & 7)) << 4),
                      g_bh + (size_t)(j0 + row) * SS + u * 8);
        } else {
            int i = f - 512;
            cpasync16(sb + BG_BSQ(stage) + i * 16, g_bsq + j0 + i * 4);
        }
    }
}

__global__ void __launch_bounds__(256, 2) kBg() {
    extern __shared__ char smem[];
    const int qb = blockIdx.x, ns = blockIdx.y;
    const int tid = threadIdx.x, wid = tid >> 5, lane = tid & 31;
    const uint32_t sb = smem_u32(smem);

    for (int f = tid; f < 512; f += 256) {
        int row = f >> 2, u = f & 3;
        uint4 v = ((const uint4*)g_bh)[(size_t)(qb * 128 + row) * 4 + u];
        *(uint4*)(smem + BG_A + row * 128 + (((u) ^ (row & 7)) << 4)) = v;
    }
    bg_load(0, 0, ns, sb, tid); CP_COMMIT();
    bg_load(1, 1, ns, sb, tid); CP_COMMIT();
    __syncthreads();

    const int rA = lane & 15, chA = lane >> 4;
    const int arow = wid * 16 + rA;
    uint32_t af[2][4];
#pragma unroll
    for (int ks = 0; ks < 2; ks++)
        ldsm4(af[ks][0], af[ks][1], af[ks][2], af[ks][3],
              sb + BG_A + arow * 128 + (((2 * ks + chA) ^ (arow & 7)) << 4));

    const int qrow = lane >> 2, qcol = lane & 3;
    const int qg0 = qb * 128 + wid * 16 + qrow;
    const int qg1 = qg0 + 8;
    const float INF = __int_as_float(0x7f800000);
    float ts0[5], ts1[5]; int ti0[5], ti1[5];
#pragma unroll
    for (int k = 0; k < 5; k++) {
        ts0[k] = INF; ts1[k] = INF; ti0[k] = 0x7fffffff; ti1[k] = 0x7fffffff;
    }
    const int rB = ((lane >> 4) << 3) + (lane & 7), chB = (lane >> 3) & 1;

    for (int it = 0; it < 16; it++) {
        CP_WAIT1();
        __syncthreads();
        int st = it & 1;
        uint32_t SB = sb + BG_S(st);
        const float* sbq = (const float*)(smem + BG_BSQ(st));
        int j0 = ns * 2048 + it * 128;
#pragma unroll
        for (int p = 0; p < 8; p++) {
            int brow = p * 16 + rB;
            uint32_t ba = SB + brow * 128;
            int bx = brow & 7;
            uint32_t b0[4], b1[4];
            ldsm4(b0[0], b0[1], b0[2], b0[3], ba + (((0 + chB) ^ bx) << 4));
            ldsm4(b1[0], b1[1], b1[2], b1[3], ba + (((2 + chB) ^ bx) << 4));
            float acc[2][4] = {};
            hmma(acc[0], af[0], &b0[0]);
            hmma(acc[1], af[0], &b0[2]);
            hmma(acc[0], af[1], &b1[0]);
            hmma(acc[1], af[1], &b1[2]);
#pragma unroll
            for (int n2 = 0; n2 < 2; n2++) {
#pragma unroll
                for (int e = 0; e < 2; e++) {
                    int cl = p * 16 + n2 * 8 + qcol * 2 + e;
                    float bq = sbq[cl];
                    int j = j0 + cl;
                    float sc0 = fmaf(-2.0f, acc[n2][e], bq);
                    float sc1 = fmaf(-2.0f, acc[n2][2 + e], bq);
                    if (j != qg0) ins5(sc0, j, ts0, ti0);
                    if (j != qg1) ins5(sc1, j, ts1, ti1);
                }
            }
        }
        __syncthreads();
        if (it < 14) bg_load(it + 2, it & 1, ns, sb, tid);
        CP_COMMIT();
    }
    CP_WAIT0();
    __syncthreads();

    float* ms = (float*)(smem + BG_MS);
    int*   mi = (int*)(smem + BG_MI);
    {
        int r0 = wid * 16 + qrow, r1 = r0 + 8;
#pragma unroll
        for (int k = 0; k < 5; k++) {
            ms[(r0 * 4 + qcol) * 5 + k] = ts0[k]; mi[(r0 * 4 + qcol) * 5 + k] = ti0[k];
            ms[(r1 * 4 + qcol) * 5 + k] = ts1[k]; mi[(r1 * 4 + qcol) * 5 + k] = ti1[k];
        }
    }
    __syncthreads();
    if (tid < 128) {
        int p4[4] = {0, 0, 0, 0};
        int q = qb * 128 + tid;
#pragma unroll
        for (int slot = 0; slot < 8; slot++) {
            float bsc = INF; int bidx = 0x7fffffff, bg = 0;
#pragma unroll
            for (int g = 0; g < 4; g++) {
                if (p4[g] < 5) {
                    float s = ms[(tid * 4 + g) * 5 + p4[g]];
                    int i = mi[(tid * 4 + g) * 5 + p4[g]];
                    if (s < bsc || (s == bsc && i < bidx)) { bsc = s; bidx = i; bg = g; }
                }
            }
            g_p8i[q * 32 + ns * 8 + slot] = bidx;
            p4[bg]++;
        }
    }
}

// ---------------- kernel B3D: exact rescore + choice + pos_sim --------------
__global__ void kB3D(const float* __restrict__ bs) {
    __shared__ float qr[8][32];
    int tid = threadIdx.x, wid = tid >> 5, lane = tid & 31;
    int q = blockIdx.x * 8 + wid;
    qr[wid][lane] = bs[(size_t)q * SS + lane];
    __syncwarp();
    int j = g_p8i[q * 32 + lane];
    const float4* cp4 = (const float4*)(bs + (size_t)j * SS);
    const float4* qp4 = (const float4*)qr[wid];
    float dot = 0.0f;
#pragma unroll
    for (int k = 0; k < 8; k++) {
        float4 cv = cp4[k], qv = qp4[k];
        dot += qv.x * cv.x + qv.y * cv.y + qv.z * cv.z + qv.w * cv.w;
    }
    float s = g_bsq[j] - 2.0f * dot;
    int id = j;
    const float INF = __int_as_float(0x7f800000);
    int c = jax_choice5((unsigned)q);
    int chosen = 0;
#pragma unroll
    for (int slot = 0; slot < 5; slot++) {
        float msv = s; int miv = id;
#pragma unroll
        for (int o = 16; o > 0; o >>= 1) {
            float os = __shfl_xor_sync(0xffffffffu, msv, o);
            int oi = __shfl_xor_sync(0xffffffffu, miv, o);
            if (os < msv || (os == msv && oi < miv)) { msv = os; miv = oi; }
        }
        if (slot == c) chosen = miv;
        if (id == miv) s = INF;
    }
    chosen = __shfl_sync(0xffffffffu, chosen, 0);
    uint4 ur = ((const uint4*)(g_znb + (size_t)q * DD))[lane];
    uint4 up = ((const uint4*)(g_znb + (size_t)chosen * DD))[lane];
    const __nv_bfloat162* br = (const __nv_bfloat162*)&ur;
    const __nv_bfloat162* bp = (const __nv_bfloat162*)&up;
    float acc = 0.0f;
#pragma unroll
    for (int e = 0; e < 4; e++) {
        float2 fr = __bfloat1622float2(br[e]);
        float2 fp = __bfloat1622float2(bp[e]);
        acc += fr.x * fp.x + fr.y * fp.y;
    }
    acc = warpsum(acc);
    if (lane == 0) g_possim[q] = acc;
}

// ---------------- kernel C: 128x64 tile HMMA, 2 CTAs/SM ---------------------
// 4160 blocks x 256 thr (4x2 warps, 32x32 warp tile). K=256 in 4 chunks of 64,
// cp.async double-buffered (A+B per stage). Per-element triangular weights.
#define KC_AS(s) ((s) * 24576)
#define KC_BSo(s) ((s) * 24576 + 16384)
#define KC_CA   49152
#define KC_SD   49664
#define KC_CB   50176
#define KC_RS   50432
#define KC_CS   50944
#define KC_RED  51200
#define KC_SMEM 51328

__device__ __forceinline__ void kc_load(int bi, int bj, int chunk, int stage,
                                        uint32_t sb, int tid) {
#pragma unroll
    for (int i = 0; i < 4; i++) {
        int f = tid + i * 256;
        int row = f >> 3, u = f & 7;
        cpasync16(sb + KC_AS(stage) + row * 128 + ((u ^ (row & 7)) << 4),
                  g_znb + (size_t)(bi * 128 + row) * DD + chunk * 64 + u * 8);
    }
#pragma unroll
    for (int i = 0; i < 2; i++) {
        int f = tid + i * 256;
        int row = f >> 3, u = f & 7;
        cpasync16(sb + KC_BSo(stage) + row * 128 + ((u ^ (row & 7)) << 4),
                  g_znb + (size_t)(bj * 64 + row) * DD + chunk * 64 + u * 8);
    }
}

__global__ void __launch_bounds__(256, 2) kC() {
    extern __shared__ char smem[];
    const int tid = threadIdx.x, wid = tid >> 5, lane = tid & 31;
    const int warp_m = wid >> 1, warp_n = wid & 1;
    const uint32_t sb = smem_u32(smem);

    // block -> (bi [128-row], bj [64-col]) with bj in [2*bi, 128)
    int t = blockIdx.x, bi = 0;
    for (;;) { int cnt = 128 - 2 * bi; if (t < cnt) break; t -= cnt; bi++; }
    const int bj = 2 * bi + t;

    float* ca = (float*)(smem + KC_CA);
    float* sdg = (float*)(smem + KC_SD);
    float* cb = (float*)(smem + KC_CB);
    float* rsum = (float*)(smem + KC_RS);
    float* csum = (float*)(smem + KC_CS);
    float* red = (float*)(smem + KC_RED);

    kc_load(bi, bj, 0, 0, sb, tid); CP_COMMIT();
    kc_load(bi, bj, 1, 1, sb, tid); CP_COMMIT();

    if (tid < 128) {
        rsum[tid] = 0.0f;
        ca[tid] = g_cexp[bi * 128 + tid];
        sdg[tid] = g_sdiag[bi * 128 + tid];
    }
    if (tid < 64) {
        csum[tid] = 0.0f;
        cb[tid] = g_cexp[bj * 64 + tid];
    }

    const int rA = lane & 15, chA = lane >> 4;
    const int rB = ((lane >> 4) << 3) + (lane & 7), chB = (lane >> 3) & 1;
    uint32_t aoff[2], boff[2];
    int ax[2], bx[2];
#pragma unroll
    for (int mi = 0; mi < 2; mi++) {
        int row = warp_m * 32 + mi * 16 + rA;
        aoff[mi] = row * 128; ax[mi] = row & 7;
    }
#pragma unroll
    for (int nb = 0; nb < 2; nb++) {
        int row = warp_n * 32 + nb * 16 + rB;
        boff[nb] = row * 128; bx[nb] = row & 7;
    }

    float acc[2][4][4] = {};
#pragma unroll
    for (int kc = 0; kc < 4; kc++) {
        if (kc < 3) { CP_WAIT1(); } else { CP_WAIT0(); }
        __syncthreads();
        uint32_t SA = sb + KC_AS(kc & 1), SB = sb + KC_BSo(kc & 1);
#pragma unroll
        for (int ks = 0; ks < 4; ks++) {
            uint32_t af[2][4], bf[2][4];
#pragma unroll
            for (int mi = 0; mi < 2; mi++)
                ldsm4(af[mi][0], af[mi][1], af[mi][2], af[mi][3],
                      SA + aoff[mi] + (((2 * ks + chA) ^ ax[mi]) << 4));
#pragma unroll
            for (int nb = 0; nb < 2; nb++)
                ldsm4(bf[nb][0], bf[nb][1], bf[nb][2], bf[nb][3],
                      SB + boff[nb] + (((2 * ks + chB) ^ bx[nb]) << 4));
#pragma unroll
            for (int mi = 0; mi < 2; mi++)
#pragma unroll
                for (int ni = 0; ni < 4; ni++)
                    hmma(acc[mi][ni], af[mi], &bf[ni >> 1][(ni & 1) * 2]);
        }
        __syncthreads();
        if (kc < 2) { kc_load(bi, bj, kc + 2, kc & 1, sb, tid); CP_COMMIT(); }
    }

    // epilogue: per-element triangular weights (w: grow<=gcol, wc: grow<gcol)
    const int qrow = lane >> 2, qcol = (lane & 3) * 2;
    const int growb = bi * 128, gcolb = bj * 64;
    float usum = 0.0f;
    float rowacc[2][2] = {};
    float colacc[4][2] = {};
#pragma unroll
    for (int mi = 0; mi < 2; mi++) {
#pragma unroll
        for (int hh = 0; hh < 2; hh++) {
            int lr = warp_m * 32 + mi * 16 + hh * 8 + qrow;
            int grow = growb + lr;
            float cav = ca[lr];
            float sdv = sdg[lr];
#pragma unroll
            for (int ni = 0; ni < 4; ni++) {
#pragma unroll
                for (int e = 0; e < 2; e++) {
                    int lc = warp_n * 32 + ni * 8 + qcol + e;
                    int gcol = gcolb + lc;
                    float s = acc[mi][ni][hh * 2 + e];
                    if (grow == gcol) s = sdv;
                    float w  = (grow <= gcol) ? 1.0f : 0.0f;
                    float wc = (grow <  gcol) ? 1.0f : 0.0f;
                    float e2 = __expf(2.0f * s);
                    float e4 = e2 * e2;
                    float e10 = e4 * e4 * e2;
                    rowacc[mi][hh] += w * e10;
                    colacc[ni][e] += wc * e10;
                    usum += (w + wc) * fminf(cav * cb[lc] * e4, 1.0f);
                }
            }
        }
    }
#pragma unroll
    for (int mi = 0; mi < 2; mi++)
#pragma unroll
        for (int hh = 0; hh < 2; hh++) {
            float v = rowacc[mi][hh];
            v += __shfl_xor_sync(0xffffffffu, v, 1);
            v += __shfl_xor_sync(0xffffffffu, v, 2);
            if ((lane & 3) == 0)
                atomicAdd(&rsum[warp_m * 32 + mi * 16 + hh * 8 + qrow], v);
        }
#pragma unroll
    for (int ni = 0; ni < 4; ni++)
#pragma unroll
        for (int e = 0; e < 2; e++) {
            float v = colacc[ni][e];
            v += __shfl_xor_sync(0xffffffffu, v, 4);
            v += __shfl_xor_sync(0xffffffffu, v, 8);
            v += __shfl_xor_sync(0xffffffffu, v, 16);
            if (lane < 4)
                atomicAdd(&csum[warp_n * 32 + ni * 8 + qcol + e], v);
        }
    usum = warpsum(usum);
    if (lane == 0) red[wid] = usum;
    __syncthreads();
    if (tid == 0) {
        float tt = 0.0f;
#pragma unroll
        for (int w = 0; w < 8; w++) tt += red[w];
        atomicAdd(&g_unif, tt);
    }
    if (tid < 128) atomicAdd(&g_denom[bi * 128 + tid], rsum[tid]);
    if (tid < 64)  atomicAdd(&g_denom[bj * 64 + tid], csum[tid]);
}

// ---------------- kernel E: final scalar (1024 thr, fast log) ---------------
__global__ void kE(float* __restrict__ out) {
    __shared__ float red[1024];
    int tid = threadIdx.x;
    float acc = 0.0f;
#pragma unroll
    for (int i = tid; i < BN; i += 1024)
        acc += __logf(g_denom[i] + 1e-8f) - g_possim[i] * 10.0f;
    red[tid] = acc;
    __syncthreads();
#pragma unroll
    for (int o = 512; o > 0; o >>= 1) {
        if (tid < o) red[tid] += red[tid + o];
        __syncthreads();
    }
    if (tid == 0) {
        float linfo = red[0] / 8192.0f;
        float lunif = __logf(g_unif * (1.0f / (8192.0f * 8192.0f)) + 1e-8f);
        out[0] = linfo + 0.1f * lunif;
    }
}

extern "C" void kernel_launch(void* const* d_in, const int* in_sizes, int n_in,
                              void* d_out, int out_size) {
    const float* z  = (const float*)d_in[0];
    const float* bs = (const float*)d_in[1];
    float* out = (float*)d_out;
    cudaFuncSetAttribute(kBg, cudaFuncAttributeMaxDynamicSharedMemorySize, KB_SMEM);
    cudaFuncSetAttribute(kC, cudaFuncAttributeMaxDynamicSharedMemorySize, KC_SMEM);

    // fork-join: binding chain (kBg->kB3D) runs concurrently with kC.
    cudaStream_t s1;
    cudaEvent_t eF, eJ;
    cudaStreamCreateWithFlags(&s1, cudaStreamNonBlocking);
    cudaEventCreateWithFlags(&eF, cudaEventDisableTiming);
    cudaEventCreateWithFlags(&eJ, cudaEventDisableTiming);

    kA<<<1024, 256>>>(z, bs);
    cudaEventRecord(eF, 0);
    cudaStreamWaitEvent(s1, eF, 0);

    kBg<<<dim3(64, 4), 256, KB_SMEM, s1>>>();
    kB3D<<<1024, 256, 0, s1>>>(bs);
    cudaEventRecord(eJ, s1);

    kC<<<4160, 256, KC_SMEM>>>();

    cudaStreamWaitEvent(0, eJ, 0);
    kE<<<1, 1024>>>(out);
    // streams/events intentionally not destroyed (capture-involved objects).
}

// round 12
// speedup vs baseline: 1.1033x; 1.0345x over previous
#include <cuda_runtime.h>
#include <cuda_bf16.h>
#include <math.h>
#include <stdint.h>

#define BN 8192
#define DD 256
#define SS 32

// ---------------- device scratch ----------------
__device__ __nv_bfloat16 g_znb[BN * DD]; // normalized z, bf16
__device__ __nv_bfloat16 g_bh[BN * SS];  // binding rows, bf16 (hi)
__device__ float g_cexp[BN];    // exp(-2*||zn_i||^2)
__device__ float g_sdiag[BN];   // ||zn_i||^2 fp32 (exact diagonal sim)
__device__ float g_bsq[BN];     // ||binding_i||^2
__device__ float g_denom[BN];   // per-row sum exp(sim/tau)
__device__ float g_possim[BN];  // sim[i, pos[i]]
__device__ float g_unif;        // sum over all pairs exp(-2*d2)
__device__ int   g_p8i[BN * 32]; // per-(query,nsplit) approx top-8 indices

__device__ __forceinline__ float warpsum(float v) {
#pragma unroll
    for (int o = 16; o > 0; o >>= 1) v += __shfl_down_sync(0xffffffffu, v, o);
    return v;
}
__device__ __forceinline__ uint32_t smem_u32(const void* p) {
    uint32_t a;
    asm("{ .reg .u64 t; cvta.to.shared.u64 t, %1; cvt.u32.u64 %0, t; }" : "=r"(a) : "l"(p));
    return a;
}
__device__ __forceinline__ void ldsm4(uint32_t& r0, uint32_t& r1, uint32_t& r2, uint32_t& r3, uint32_t a) {
    asm volatile("ldmatrix.sync.aligned.m8n8.x4.shared.b16 {%0,%1,%2,%3}, [%4];"
                 : "=r"(r0), "=r"(r1), "=r"(r2), "=r"(r3) : "r"(a));
}
__device__ __forceinline__ void hmma(float* c, const uint32_t* a, const uint32_t* b) {
    asm volatile(
        "mma.sync.aligned.m16n8k16.row.col.f32.bf16.bf16.f32 "
        "{%0,%1,%2,%3}, {%4,%5,%6,%7}, {%8,%9}, {%0,%1,%2,%3};"
        : "+f"(c[0]), "+f"(c[1]), "+f"(c[2]), "+f"(c[3])
        : "r"(a[0]), "r"(a[1]), "r"(a[2]), "r"(a[3]), "r"(b[0]), "r"(b[1]));
}
__device__ __forceinline__ void cpasync16(uint32_t dst, const void* src) {
    asm volatile("cp.async.ca.shared.global [%0], [%1], 16;"
                 :: "r"(dst), "l"(__cvta_generic_to_global(src)) : "memory");
}
#define CP_COMMIT() asm volatile("cp.async.commit_group;" ::: "memory")
#define CP_WAIT1()  asm volatile("cp.async.wait_group 1;" ::: "memory")
#define CP_WAIT0()  asm volatile("cp.async.wait_group 0;" ::: "memory")

// sorted-5 insert, strict < keeps lowest-index-first on ties
__device__ __forceinline__ void ins5(float sc, int j, float* s, int* id) {
    if (sc < s[4]) {
        if (sc < s[2]) {
            s[4] = s[3]; id[4] = id[3]; s[3] = s[2]; id[3] = id[2];
            if (sc < s[1]) {
                s[2] = s[1]; id[2] = id[1];
                if (sc < s[0]) { s[1] = s[0]; id[1] = id[0]; s[0] = sc; id[0] = j; }
                else           { s[1] = sc; id[1] = j; }
            } else             { s[2] = sc; id[2] = j; }
        } else {
            if (sc < s[3]) { s[4] = s[3]; id[4] = id[3]; s[3] = sc; id[3] = j; }
            else           { s[4] = sc; id[4] = j; }
        }
    }
}

// ---------------- threefry2x32 (exact JAX, partitionable) ----------------
__device__ __forceinline__ void tf2x32(unsigned k0, unsigned k1,
                                       unsigned x0, unsigned x1,
                                       unsigned& o0, unsigned& o1) {
    unsigned ks0 = k0, ks1 = k1, ks2 = k0 ^ k1 ^ 0x1BD11BDAu;
    x0 += ks0; x1 += ks1;
#define TFR(r) { x0 += x1; x1 = (x1 << r) | (x1 >> (32 - r)); x1 ^= x0; }
    TFR(13) TFR(15) TFR(26) TFR(6)   x0 += ks1; x1 += ks2 + 1u;
    TFR(17) TFR(29) TFR(16) TFR(24)  x0 += ks2; x1 += ks0 + 2u;
    TFR(13) TFR(15) TFR(26) TFR(6)   x0 += ks0; x1 += ks1 + 3u;
    TFR(17) TFR(29) TFR(16) TFR(24)  x0 += ks1; x1 += ks2 + 4u;
    TFR(13) TFR(15) TFR(26) TFR(6)   x0 += ks2; x1 += ks0 + 5u;
#undef TFR
    o0 = x0; o1 = x1;
}
__device__ __forceinline__ int jax_choice5(unsigned i) {
    unsigned a, b, k1a, k1b, k2a, k2b;
    tf2x32(0u, 42u, 0u, 0u, k1a, k1b);
    tf2x32(0u, 42u, 0u, 1u, k2a, k2b);
    tf2x32(k1a, k1b, 0u, i, a, b); unsigned h = a ^ b;
    tf2x32(k2a, k2b, 0u, i, a, b); unsigned l = a ^ b;
    return (int)(((h % 5u) + (l % 5u)) % 5u);
}

// ---------------- kernel A: normalize -> bf16, norms, packs -----------------
__global__ void kA(const float* __restrict__ z, const float* __restrict__ bs) {
    int w = threadIdx.x >> 5, lane = threadIdx.x & 31;
    int r = blockIdx.x * 8 + w;
    const float4* zr = (const float4*)(z + (size_t)r * DD);
    float4 a = zr[2 * lane];
    float4 b = zr[2 * lane + 1];
    float ss = a.x*a.x + a.y*a.y + a.z*a.z + a.w*a.w
             + b.x*b.x + b.y*b.y + b.z*b.z + b.w*b.w;
    ss = warpsum(ss);
    ss = __shfl_sync(0xffffffffu, ss, 0);
    float inv = 1.0f / sqrtf(ss);
    __nv_bfloat162 pk[4];
    pk[0] = __floats2bfloat162_rn(a.x * inv, a.y * inv);
    pk[1] = __floats2bfloat162_rn(a.z * inv, a.w * inv);
    pk[2] = __floats2bfloat162_rn(b.x * inv, b.y * inv);
    pk[3] = __floats2bfloat162_rn(b.z * inv, b.w * inv);
    ((uint4*)(g_znb + (size_t)r * DD))[lane] = *(uint4*)pk;

    float bv = bs[(size_t)r * SS + lane];
    g_bh[r * SS + lane] = __float2bfloat16_rn(bv);
    float bq = warpsum(bv * bv);
    if (lane == 0) {
        float s2 = ss * inv * inv;
        g_cexp[r] = __expf(-2.0f * s2);
        g_sdiag[r] = s2;
        g_bsq[r] = bq;
        g_denom[r] = 0.0f;
    }
    if (blockIdx.x == 0 && threadIdx.x == 0) g_unif = 0.0f;
}

// ---------------- kernel Bg: approx (hi-only) top-8 per split ---------------
#define BG_A     0
#define BG_S(s)  (16384 + (s) * 16896)
#define BG_BSQ(s) (BG_S(s) + 16384)
#define BG_MS    0
#define BG_MI    16384
#define KB_SMEM  (16384 + 2 * 16896)

__device__ __forceinline__ void bg_load(int chunk, int stage, int ns, uint32_t sb, int tid) {
    int j0 = ns * 2048 + chunk * 128;
    for (int f = tid; f < 544; f += 256) {
        if (f < 512) {
            int row = f >> 2, u = f & 3;
            cpasync16(sb + BG_S(stage) + row * 128 + (((u) ^ (row & 7)) << 4),
                      g_bh + (size_t)(j0 + row) * SS + u * 8);
        } else {
            int i = f - 512;
            cpasync16(sb + BG_BSQ(stage) + i * 16, g_bsq + j0 + i * 4);
        }
    }
}

__global__ void __launch_bounds__(256, 2) kBg() {
    extern __shared__ char smem[];
    const int qb = blockIdx.x, ns = blockIdx.y;
    const int tid = threadIdx.x, wid = tid >> 5, lane = tid & 31;
    const uint32_t sb = smem_u32(smem);

    for (int f = tid; f < 512; f += 256) {
        int row = f >> 2, u = f & 3;
        uint4 v = ((const uint4*)g_bh)[(size_t)(qb * 128 + row) * 4 + u];
        *(uint4*)(smem + BG_A + row * 128 + (((u) ^ (row & 7)) << 4)) = v;
    }
    bg_load(0, 0, ns, sb, tid); CP_COMMIT();
    bg_load(1, 1, ns, sb, tid); CP_COMMIT();
    __syncthreads();

    const int rA = lane & 15, chA = lane >> 4;
    const int arow = wid * 16 + rA;
    uint32_t af[2][4];
#pragma unroll
    for (int ks = 0; ks < 2; ks++)
        ldsm4(af[ks][0], af[ks][1], af[ks][2], af[ks][3],
              sb + BG_A + arow * 128 + (((2 * ks + chA) ^ (arow & 7)) << 4));

    const int qrow = lane >> 2, qcol = lane & 3;
    const int qg0 = qb * 128 + wid * 16 + qrow;
    const int qg1 = qg0 + 8;
    const float INF = __int_as_float(0x7f800000);
    float ts0[5], ts1[5]; int ti0[5], ti1[5];
#pragma unroll
    for (int k = 0; k < 5; k++) {
        ts0[k] = INF; ts1[k] = INF; ti0[k] = 0x7fffffff; ti1[k] = 0x7fffffff;
    }
    const int rB = ((lane >> 4) << 3) + (lane & 7), chB = (lane >> 3) & 1;

    for (int it = 0; it < 16; it++) {
        CP_WAIT1();
        __syncthreads();
        int st = it & 1;
        uint32_t SB = sb + BG_S(st);
        const float* sbq = (const float*)(smem + BG_BSQ(st));
        int j0 = ns * 2048 + it * 128;
#pragma unroll
        for (int p = 0; p < 8; p++) {
            int brow = p * 16 + rB;
            uint32_t ba = SB + brow * 128;
            int bx = brow & 7;
            uint32_t b0[4], b1[4];
            ldsm4(b0[0], b0[1], b0[2], b0[3], ba + (((0 + chB) ^ bx) << 4));
            ldsm4(b1[0], b1[1], b1[2], b1[3], ba + (((2 + chB) ^ bx) << 4));
            float acc[2][4] = {};
            hmma(acc[0], af[0], &b0[0]);
            hmma(acc[1], af[0], &b0[2]);
            hmma(acc[0], af[1], &b1[0]);
            hmma(acc[1], af[1], &b1[2]);
#pragma unroll
            for (int n2 = 0; n2 < 2; n2++) {
#pragma unroll
                for (int e = 0; e < 2; e++) {
                    int cl = p * 16 + n2 * 8 + qcol * 2 + e;
                    float bq = sbq[cl];
                    int j = j0 + cl;
                    float sc0 = fmaf(-2.0f, acc[n2][e], bq);
                    float sc1 = fmaf(-2.0f, acc[n2][2 + e], bq);
                    if (j != qg0) ins5(sc0, j, ts0, ti0);
                    if (j != qg1) ins5(sc1, j, ts1, ti1);
                }
            }
        }
        __syncthreads();
        if (it < 14) bg_load(it + 2, it & 1, ns, sb, tid);
        CP_COMMIT();
    }
    CP_WAIT0();
    __syncthreads();

    float* ms = (float*)(smem + BG_MS);
    int*   mi = (int*)(smem + BG_MI);
    {
        int r0 = wid * 16 + qrow, r1 = r0 + 8;
#pragma unroll
        for (int k = 0; k < 5; k++) {
            ms[(r0 * 4 + qcol) * 5 + k] = ts0[k]; mi[(r0 * 4 + qcol) * 5 + k] = ti0[k];
            ms[(r1 * 4 + qcol) * 5 + k] = ts1[k]; mi[(r1 * 4 + qcol) * 5 + k] = ti1[k];
        }
    }
    __syncthreads();
    if (tid < 128) {
        int p4[4] = {0, 0, 0, 0};
        int q = qb * 128 + tid;
#pragma unroll
        for (int slot = 0; slot < 8; slot++) {
            float bsc = INF; int bidx = 0x7fffffff, bg = 0;
#pragma unroll
            for (int g = 0; g < 4; g++) {
                if (p4[g] < 5) {
                    float s = ms[(tid * 4 + g) * 5 + p4[g]];
                    int i = mi[(tid * 4 + g) * 5 + p4[g]];
                    if (s < bsc || (s == bsc && i < bidx)) { bsc = s; bidx = i; bg = g; }
                }
            }
            g_p8i[q * 32 + ns * 8 + slot] = bidx;
            p4[bg]++;
        }
    }
}

// ---------------- kernel B3D: exact rescore + choice + pos_sim --------------
__global__ void kB3D(const float* __restrict__ bs) {
    __shared__ float qr[8][32];
    int tid = threadIdx.x, wid = tid >> 5, lane = tid & 31;
    int q = blockIdx.x * 8 + wid;
    qr[wid][lane] = bs[(size_t)q * SS + lane];
    __syncwarp();
    int j = g_p8i[q * 32 + lane];
    const float4* cp4 = (const float4*)(bs + (size_t)j * SS);
    const float4* qp4 = (const float4*)qr[wid];
    float dot = 0.0f;
#pragma unroll
    for (int k = 0; k < 8; k++) {
        float4 cv = cp4[k], qv = qp4[k];
        dot += qv.x * cv.x + qv.y * cv.y + qv.z * cv.z + qv.w * cv.w;
    }
    float s = g_bsq[j] - 2.0f * dot;
    int id = j;
    const float INF = __int_as_float(0x7f800000);
    int c = jax_choice5((unsigned)q);
    int chosen = 0;
#pragma unroll
    for (int slot = 0; slot < 5; slot++) {
        float msv = s; int miv = id;
#pragma unroll
        for (int o = 16; o > 0; o >>= 1) {
            float os = __shfl_xor_sync(0xffffffffu, msv, o);
            int oi = __shfl_xor_sync(0xffffffffu, miv, o);
            if (os < msv || (os == msv && oi < miv)) { msv = os; miv = oi; }
        }
        if (slot == c) chosen = miv;
        if (id == miv) s = INF;
    }
    chosen = __shfl_sync(0xffffffffu, chosen, 0);
    uint4 ur = ((const uint4*)(g_znb + (size_t)q * DD))[lane];
    uint4 up = ((const uint4*)(g_znb + (size_t)chosen * DD))[lane];
    const __nv_bfloat162* br = (const __nv_bfloat162*)&ur;
    const __nv_bfloat162* bp = (const __nv_bfloat162*)&up;
    float acc = 0.0f;
#pragma unroll
    for (int e = 0; e < 4; e++) {
        float2 fr = __bfloat1622float2(br[e]);
        float2 fp = __bfloat1622float2(bp[e]);
        acc += fr.x * fp.x + fr.y * fp.y;
    }
    acc = warpsum(acc);
    if (lane == 0) g_possim[q] = acc;
}

// ---------------- kernel C: 128x64 tile HMMA, 2 CTAs/SM ---------------------
// 4160 blocks x 256 thr (4x2 warps, 32x32 warp tile). K=256 in 4 chunks of 64,
// cp.async double-buffered. Epilogue specialized: off-diag fast / diag weighted.
#define KC_AS(s) ((s) * 24576)
#define KC_BSo(s) ((s) * 24576 + 16384)
#define KC_CA   49152
#define KC_SD   49664
#define KC_CB   50176
#define KC_RS   50432
#define KC_CS   50944
#define KC_RED  51200
#define KC_SMEM 51328

__device__ __forceinline__ void kc_load(int bi, int bj, int chunk, int stage,
                                        uint32_t sb, int tid) {
#pragma unroll
    for (int i = 0; i < 4; i++) {
        int f = tid + i * 256;
        int row = f >> 3, u = f & 7;
        cpasync16(sb + KC_AS(stage) + row * 128 + ((u ^ (row & 7)) << 4),
                  g_znb + (size_t)(bi * 128 + row) * DD + chunk * 64 + u * 8);
    }
#pragma unroll
    for (int i = 0; i < 2; i++) {
        int f = tid + i * 256;
        int row = f >> 3, u = f & 7;
        cpasync16(sb + KC_BSo(stage) + row * 128 + ((u ^ (row & 7)) << 4),
                  g_znb + (size_t)(bj * 64 + row) * DD + chunk * 64 + u * 8);
    }
}

__global__ void __launch_bounds__(256, 2) kC() {
    extern __shared__ char smem[];
    const int tid = threadIdx.x, wid = tid >> 5, lane = tid & 31;
    const int warp_m = wid >> 1, warp_n = wid & 1;
    const uint32_t sb = smem_u32(smem);

    // closed-form block -> (bi, bj): cum(bi) = 129*bi - bi^2; bj in [2bi,128)
    int t = blockIdx.x;
    int bi = (int)(0.5f * (129.0f - sqrtf(fmaxf(16641.0f - 4.0f * (float)t, 0.0f))));
    while (bi > 0 && 129 * bi - bi * bi > t) bi--;
    while (129 * (bi + 1) - (bi + 1) * (bi + 1) <= t) bi++;
    const int bj = 2 * bi + (t - (129 * bi - bi * bi));
    const bool diagblk = (bj >> 1) == bi;   // bj == 2bi or 2bi+1

    float* ca = (float*)(smem + KC_CA);
    float* sdg = (float*)(smem + KC_SD);
    float* cb = (float*)(smem + KC_CB);
    float* rsum = (float*)(smem + KC_RS);
    float* csum = (float*)(smem + KC_CS);
    float* red = (float*)(smem + KC_RED);

    kc_load(bi, bj, 0, 0, sb, tid); CP_COMMIT();
    kc_load(bi, bj, 1, 1, sb, tid); CP_COMMIT();

    if (tid < 128) {
        rsum[tid] = 0.0f;
        ca[tid] = g_cexp[bi * 128 + tid];
        sdg[tid] = g_sdiag[bi * 128 + tid];
    }
    if (tid < 64) {
        csum[tid] = 0.0f;
        cb[tid] = g_cexp[bj * 64 + tid];
    }

    const int rA = lane & 15, chA = lane >> 4;
    const int rB = ((lane >> 4) << 3) + (lane & 7), chB = (lane >> 3) & 1;
    uint32_t aoff[2], boff[2];
    int ax[2], bx[2];
#pragma unroll
    for (int mi = 0; mi < 2; mi++) {
        int row = warp_m * 32 + mi * 16 + rA;
        aoff[mi] = row * 128; ax[mi] = row & 7;
    }
#pragma unroll
    for (int nb = 0; nb < 2; nb++) {
        int row = warp_n * 32 + nb * 16 + rB;
        boff[nb] = row * 128; bx[nb] = row & 7;
    }

    float acc[2][4][4] = {};
#pragma unroll
    for (int kc = 0; kc < 4; kc++) {
        if (kc < 3) { CP_WAIT1(); } else { CP_WAIT0(); }
        __syncthreads();
        uint32_t SA = sb + KC_AS(kc & 1), SB = sb + KC_BSo(kc & 1);
#pragma unroll
        for (int ks = 0; ks < 4; ks++) {
            uint32_t af[2][4], bf[2][4];
#pragma unroll
            for (int mi = 0; mi < 2; mi++)
                ldsm4(af[mi][0], af[mi][1], af[mi][2], af[mi][3],
                      SA + aoff[mi] + (((2 * ks + chA) ^ ax[mi]) << 4));
#pragma unroll
            for (int nb = 0; nb < 2; nb++)
                ldsm4(bf[nb][0], bf[nb][1], bf[nb][2], bf[nb][3],
                      SB + boff[nb] + (((2 * ks + chB) ^ bx[nb]) << 4));
#pragma unroll
            for (int mi = 0; mi < 2; mi++)
#pragma unroll
                for (int ni = 0; ni < 4; ni++)
                    hmma(acc[mi][ni], af[mi], &bf[ni >> 1][(ni & 1) * 2]);
        }
        __syncthreads();
        if (kc < 2) { kc_load(bi, bj, kc + 2, kc & 1, sb, tid); CP_COMMIT(); }
    }

    const int qrow = lane >> 2, qcol = (lane & 3) * 2;
    float usum = 0.0f;
    float rowacc[2][2] = {};
    float colacc[4][2] = {};
    if (!diagblk) {
        // fast path: strictly above diagonal, uniform weights
#pragma unroll
        for (int mi = 0; mi < 2; mi++) {
#pragma unroll
            for (int hh = 0; hh < 2; hh++) {
                int lr = warp_m * 32 + mi * 16 + hh * 8 + qrow;
                float cav = ca[lr];
#pragma unroll
                for (int ni = 0; ni < 4; ni++) {
#pragma unroll
                    for (int e = 0; e < 2; e++) {
                        int lc = warp_n * 32 + ni * 8 + qcol + e;
                        float s = acc[mi][ni][hh * 2 + e];
                        float e2 = __expf(2.0f * s);
                        float e4 = e2 * e2;
                        float e10 = e4 * e4 * e2;
                        rowacc[mi][hh] += e10;
                        colacc[ni][e] += e10;
                        usum += 2.0f * fminf(cav * cb[lc] * e4, 1.0f);
                    }
                }
            }
        }
    } else {
        // diagonal-touching block: per-element weights + exact fp32 diagonal
        const int growb = bi * 128, gcolb = bj * 64;
#pragma unroll
        for (int mi = 0; mi < 2; mi++) {
#pragma unroll
            for (int hh = 0; hh < 2; hh++) {
                int lr = warp_m * 32 + mi * 16 + hh * 8 + qrow;
                int grow = growb + lr;
                float cav = ca[lr];
                float sdv = sdg[lr];
#pragma unroll
                for (int ni = 0; ni < 4; ni++) {
#pragma unroll
                    for (int e = 0; e < 2; e++) {
                        int lc = warp_n * 32 + ni * 8 + qcol + e;
                        int gcol = gcolb + lc;
                        float s = acc[mi][ni][hh * 2 + e];
                        if (grow == gcol) s = sdv;
                        float w  = (grow <= gcol) ? 1.0f : 0.0f;
                        float wc = (grow <  gcol) ? 1.0f : 0.0f;
                        float e2 = __expf(2.0f * s);
                        float e4 = e2 * e2;
                        float e10 = e4 * e4 * e2;
                        rowacc[mi][hh] += w * e10;
                        colacc[ni][e] += wc * e10;
                        usum += (w + wc) * fminf(cav * cb[lc] * e4, 1.0f);
                    }
                }
            }
        }
    }
#pragma unroll
    for (int mi = 0; mi < 2; mi++)
#pragma unroll
        for (int hh = 0; hh < 2; hh++) {
            float v = rowacc[mi][hh];
            v += __shfl_xor_sync(0xffffffffu, v, 1);
            v += __shfl_xor_sync(0xffffffffu, v, 2);
            if ((lane & 3) == 0)
                atomicAdd(&rsum[warp_m * 32 + mi * 16 + hh * 8 + qrow], v);
        }
#pragma unroll
    for (int ni = 0; ni < 4; ni++)
#pragma unroll
        for (int e = 0; e < 2; e++) {
            float v = colacc[ni][e];
            v += __shfl_xor_sync(0xffffffffu, v, 4);
            v += __shfl_xor_sync(0xffffffffu, v, 8);
            v += __shfl_xor_sync(0xffffffffu, v, 16);
            if (lane < 4)
                atomicAdd(&csum[warp_n * 32 + ni * 8 + qcol + e], v);
        }
    usum = warpsum(usum);
    if (lane == 0) red[wid] = usum;
    __syncthreads();
    if (tid == 0) {
        float tt = 0.0f;
#pragma unroll
        for (int w = 0; w < 8; w++) tt += red[w];
        atomicAdd(&g_unif, tt);
    }
    if (tid < 128) atomicAdd(&g_denom[bi * 128 + tid], rsum[tid]);
    if (tid < 64)  atomicAdd(&g_denom[bj * 64 + tid], csum[tid]);
}

// ---------------- kernel E: final scalar (1024 thr, fast log) ---------------
__global__ void kE(float* __restrict__ out) {
    __shared__ float red[1024];
    int tid = threadIdx.x;
    float acc = 0.0f;
#pragma unroll
    for (int i = tid; i < BN; i += 1024)
        acc += __logf(g_denom[i] + 1e-8f) - g_possim[i] * 10.0f;
    red[tid] = acc;
    __syncthreads();
#pragma unroll
    for (int o = 512; o > 0; o >>= 1) {
        if (tid < o) red[tid] += red[tid + o];
        __syncthreads();
    }
    if (tid == 0) {
        float linfo = red[0] / 8192.0f;
        float lunif = __logf(g_unif * (1.0f / (8192.0f * 8192.0f)) + 1e-8f);
        out[0] = linfo + 0.1f * lunif;
    }
}

extern "C" void kernel_launch(void* const* d_in, const int* in_sizes, int n_in,
                              void* d_out, int out_size) {
    const float* z  = (const float*)d_in[0];
    const float* bs = (const float*)d_in[1];
    float* out = (float*)d_out;
    cudaFuncSetAttribute(kBg, cudaFuncAttributeMaxDynamicSharedMemorySize, KB_SMEM);
    cudaFuncSetAttribute(kC, cudaFuncAttributeMaxDynamicSharedMemorySize, KC_SMEM);

    // fork-join: binding chain (kBg->kB3D) runs concurrently with kC.
    cudaStream_t s1;
    cudaEvent_t eF, eJ;
    cudaStreamCreateWithFlags(&s1, cudaStreamNonBlocking);
    cudaEventCreateWithFlags(&eF, cudaEventDisableTiming);
    cudaEventCreateWithFlags(&eJ, cudaEventDisableTiming);

    kA<<<1024, 256>>>(z, bs);
    cudaEventRecord(eF, 0);
    cudaStreamWaitEvent(s1, eF, 0);

    kBg<<<dim3(64, 4), 256, KB_SMEM, s1>>>();
    kB3D<<<1024, 256, 0, s1>>>(bs);
    cudaEventRecord(eJ, s1);

    kC<<<4160, 256, KC_SMEM>>>();

    cudaStreamWaitEvent(0, eJ, 0);
    kE<<<1, 1024>>>(out);
    // streams/events intentionally not destroyed (capture-involved objects).
}

// round 13
// speedup vs baseline: 1.3106x; 1.1879x over previous
#include <cuda_runtime.h>
#include <cuda_bf16.h>
#include <math.h>
#include <stdint.h>

#define BN 8192
#define DD 256
#define SS 32

// ---------------- device scratch ----------------
__device__ __nv_bfloat16 g_znb[BN * DD]; // normalized z, bf16
__device__ __nv_bfloat16 g_bh[BN * SS];  // binding rows, bf16 (hi)
__device__ float g_cexp[BN];    // exp(-2*||zn_i||^2)
__device__ float g_sdiag[BN];   // ||zn_i||^2 fp32 (exact diagonal sim)
__device__ float g_bsq[BN];     // ||binding_i||^2
__device__ float g_denom[BN];   // per-row sum exp(sim/tau)
__device__ float g_possim[BN];  // sim[i, pos[i]]
__device__ float g_unif;        // sum over all pairs exp(-2*d2)
__device__ int   g_p8i[BN * 32]; // per-(query,nsplit) approx top-8 indices

__device__ __forceinline__ float warpsum(float v) {
#pragma unroll
    for (int o = 16; o > 0; o >>= 1) v += __shfl_down_sync(0xffffffffu, v, o);
    return v;
}
__device__ __forceinline__ uint32_t smem_u32(const void* p) {
    uint32_t a;
    asm("{ .reg .u64 t; cvta.to.shared.u64 t, %1; cvt.u32.u64 %0, t; }" : "=r"(a) : "l"(p));
    return a;
}
__device__ __forceinline__ void ldsm4(uint32_t& r0, uint32_t& r1, uint32_t& r2, uint32_t& r3, uint32_t a) {
    asm volatile("ldmatrix.sync.aligned.m8n8.x4.shared.b16 {%0,%1,%2,%3}, [%4];"
                 : "=r"(r0), "=r"(r1), "=r"(r2), "=r"(r3) : "r"(a));
}
__device__ __forceinline__ void hmma(float* c, const uint32_t* a, const uint32_t* b) {
    asm volatile(
        "mma.sync.aligned.m16n8k16.row.col.f32.bf16.bf16.f32 "
        "{%0,%1,%2,%3}, {%4,%5,%6,%7}, {%8,%9}, {%0,%1,%2,%3};"
        : "+f"(c[0]), "+f"(c[1]), "+f"(c[2]), "+f"(c[3])
        : "r"(a[0]), "r"(a[1]), "r"(a[2]), "r"(a[3]), "r"(b[0]), "r"(b[1]));
}
__device__ __forceinline__ void cpasync16(uint32_t dst, const void* src) {
    asm volatile("cp.async.ca.shared.global [%0], [%1], 16;"
                 :: "r"(dst), "l"(__cvta_generic_to_global(src)) : "memory");
}
#define CP_COMMIT() asm volatile("cp.async.commit_group;" ::: "memory")
#define CP_WAIT1()  asm volatile("cp.async.wait_group 1;" ::: "memory")
#define CP_WAIT0()  asm volatile("cp.async.wait_group 0;" ::: "memory")

// sorted-5 insert, strict < keeps lowest-index-first on ties
__device__ __forceinline__ void ins5(float sc, int j, float* s, int* id) {
    if (sc < s[4]) {
        if (sc < s[2]) {
            s[4] = s[3]; id[4] = id[3]; s[3] = s[2]; id[3] = id[2];
            if (sc < s[1]) {
                s[2] = s[1]; id[2] = id[1];
                if (sc < s[0]) { s[1] = s[0]; id[1] = id[0]; s[0] = sc; id[0] = j; }
                else           { s[1] = sc; id[1] = j; }
            } else             { s[2] = sc; id[2] = j; }
        } else {
            if (sc < s[3]) { s[4] = s[3]; id[4] = id[3]; s[3] = sc; id[3] = j; }
            else           { s[4] = sc; id[4] = j; }
        }
    }
}

// ---------------- threefry2x32 (exact JAX, partitionable) ----------------
__device__ __forceinline__ void tf2x32(unsigned k0, unsigned k1,
                                       unsigned x0, unsigned x1,
                                       unsigned& o0, unsigned& o1) {
    unsigned ks0 = k0, ks1 = k1, ks2 = k0 ^ k1 ^ 0x1BD11BDAu;
    x0 += ks0; x1 += ks1;
#define TFR(r) { x0 += x1; x1 = (x1 << r) | (x1 >> (32 - r)); x1 ^= x0; }
    TFR(13) TFR(15) TFR(26) TFR(6)   x0 += ks1; x1 += ks2 + 1u;
    TFR(17) TFR(29) TFR(16) TFR(24)  x0 += ks2; x1 += ks0 + 2u;
    TFR(13) TFR(15) TFR(26) TFR(6)   x0 += ks0; x1 += ks1 + 3u;
    TFR(17) TFR(29) TFR(16) TFR(24)  x0 += ks1; x1 += ks2 + 4u;
    TFR(13) TFR(15) TFR(26) TFR(6)   x0 += ks2; x1 += ks0 + 5u;
#undef TFR
    o0 = x0; o1 = x1;
}
__device__ __forceinline__ int jax_choice5(unsigned i) {
    unsigned a, b, k1a, k1b, k2a, k2b;
    tf2x32(0u, 42u, 0u, 0u, k1a, k1b);
    tf2x32(0u, 42u, 0u, 1u, k2a, k2b);
    tf2x32(k1a, k1b, 0u, i, a, b); unsigned h = a ^ b;
    tf2x32(k2a, k2b, 0u, i, a, b); unsigned l = a ^ b;
    return (int)(((h % 5u) + (l % 5u)) % 5u);
}

// ---------------- kernel A: normalize -> bf16, norms, packs -----------------
__global__ void kA(const float* __restrict__ z, const float* __restrict__ bs) {
    int w = threadIdx.x >> 5, lane = threadIdx.x & 31;
    int r = blockIdx.x * 8 + w;
    const float4* zr = (const float4*)(z + (size_t)r * DD);
    float4 a = zr[2 * lane];
    float4 b = zr[2 * lane + 1];
    float ss = a.x*a.x + a.y*a.y + a.z*a.z + a.w*a.w
             + b.x*b.x + b.y*b.y + b.z*b.z + b.w*b.w;
    ss = warpsum(ss);
    ss = __shfl_sync(0xffffffffu, ss, 0);
    float inv = 1.0f / sqrtf(ss);
    __nv_bfloat162 pk[4];
    pk[0] = __floats2bfloat162_rn(a.x * inv, a.y * inv);
    pk[1] = __floats2bfloat162_rn(a.z * inv, a.w * inv);
    pk[2] = __floats2bfloat162_rn(b.x * inv, b.y * inv);
    pk[3] = __floats2bfloat162_rn(b.z * inv, b.w * inv);
    ((uint4*)(g_znb + (size_t)r * DD))[lane] = *(uint4*)pk;

    float bv = bs[(size_t)r * SS + lane];
    g_bh[r * SS + lane] = __float2bfloat16_rn(bv);
    float bq = warpsum(bv * bv);
    if (lane == 0) {
        float s2 = ss * inv * inv;
        g_cexp[r] = __expf(-2.0f * s2);
        g_sdiag[r] = s2;
        g_bsq[r] = bq;
        g_denom[r] = 0.0f;
    }
    if (blockIdx.x == 0 && threadIdx.x == 0) g_unif = 0.0f;
}

// ---------------- kernel Bg: approx (hi-only) top-8 per split ---------------
#define BG_A     0
#define BG_S(s)  (16384 + (s) * 16896)
#define BG_BSQ(s) (BG_S(s) + 16384)
#define BG_MS    0
#define BG_MI    16384
#define KB_SMEM  (16384 + 2 * 16896)

__device__ __forceinline__ void bg_load(int chunk, int stage, int ns, uint32_t sb, int tid) {
    int j0 = ns * 2048 + chunk * 128;
    for (int f = tid; f < 544; f += 256) {
        if (f < 512) {
            int row = f >> 2, u = f & 3;
            cpasync16(sb + BG_S(stage) + row * 128 + (((u) ^ (row & 7)) << 4),
                      g_bh + (size_t)(j0 + row) * SS + u * 8);
        } else {
            int i = f - 512;
            cpasync16(sb + BG_BSQ(stage) + i * 16, g_bsq + j0 + i * 4);
        }
    }
}

__global__ void __launch_bounds__(256, 3) kBg() {
    extern __shared__ char smem[];
    const int qb = blockIdx.x, ns = blockIdx.y;
    const int tid = threadIdx.x, wid = tid >> 5, lane = tid & 31;
    const uint32_t sb = smem_u32(smem);

    for (int f = tid; f < 512; f += 256) {
        int row = f >> 2, u = f & 3;
        uint4 v = ((const uint4*)g_bh)[(size_t)(qb * 128 + row) * 4 + u];
        *(uint4*)(smem + BG_A + row * 128 + (((u) ^ (row & 7)) << 4)) = v;
    }
    bg_load(0, 0, ns, sb, tid); CP_COMMIT();
    bg_load(1, 1, ns, sb, tid); CP_COMMIT();
    __syncthreads();

    const int rA = lane & 15, chA = lane >> 4;
    const int arow = wid * 16 + rA;
    uint32_t af[2][4];
#pragma unroll
    for (int ks = 0; ks < 2; ks++)
        ldsm4(af[ks][0], af[ks][1], af[ks][2], af[ks][3],
              sb + BG_A + arow * 128 + (((2 * ks + chA) ^ (arow & 7)) << 4));

    const int qrow = lane >> 2, qcol = lane & 3;
    const int qg0 = qb * 128 + wid * 16 + qrow;
    const int qg1 = qg0 + 8;
    const float INF = __int_as_float(0x7f800000);
    float ts0[5], ts1[5]; int ti0[5], ti1[5];
#pragma unroll
    for (int k = 0; k < 5; k++) {
        ts0[k] = INF; ts1[k] = INF; ti0[k] = 0x7fffffff; ti1[k] = 0x7fffffff;
    }
    const int rB = ((lane >> 4) << 3) + (lane & 7), chB = (lane >> 3) & 1;

    for (int it = 0; it < 16; it++) {
        CP_WAIT1();
        __syncthreads();
        int st = it & 1;
        uint32_t SB = sb + BG_S(st);
        const float* sbq = (const float*)(smem + BG_BSQ(st));
        int j0 = ns * 2048 + it * 128;
#pragma unroll
        for (int p = 0; p < 8; p++) {
            int brow = p * 16 + rB;
            uint32_t ba = SB + brow * 128;
            int bx = brow & 7;
            uint32_t b0[4], b1[4];
            ldsm4(b0[0], b0[1], b0[2], b0[3], ba + (((0 + chB) ^ bx) << 4));
            ldsm4(b1[0], b1[1], b1[2], b1[3], ba + (((2 + chB) ^ bx) << 4));
            float acc[2][4] = {};
            hmma(acc[0], af[0], &b0[0]);
            hmma(acc[1], af[0], &b0[2]);
            hmma(acc[0], af[1], &b1[0]);
            hmma(acc[1], af[1], &b1[2]);
#pragma unroll
            for (int n2 = 0; n2 < 2; n2++) {
#pragma unroll
                for (int e = 0; e < 2; e++) {
                    int cl = p * 16 + n2 * 8 + qcol * 2 + e;
                    float bq = sbq[cl];
                    int j = j0 + cl;
                    float sc0 = fmaf(-2.0f, acc[n2][e], bq);
                    float sc1 = fmaf(-2.0f, acc[n2][2 + e], bq);
                    if (j != qg0) ins5(sc0, j, ts0, ti0);
                    if (j != qg1) ins5(sc1, j, ts1, ti1);
                }
            }
        }
        __syncthreads();
        if (it < 14) bg_load(it + 2, it & 1, ns, sb, tid);
        CP_COMMIT();
    }
    CP_WAIT0();
    __syncthreads();

    float* ms = (float*)(smem + BG_MS);
    int*   mi = (int*)(smem + BG_MI);
    {
        int r0 = wid * 16 + qrow, r1 = r0 + 8;
#pragma unroll
        for (int k = 0; k < 5; k++) {
            ms[(r0 * 4 + qcol) * 5 + k] = ts0[k]; mi[(r0 * 4 + qcol) * 5 + k] = ti0[k];
            ms[(r1 * 4 + qcol) * 5 + k] = ts1[k]; mi[(r1 * 4 + qcol) * 5 + k] = ti1[k];
        }
    }
    __syncthreads();
    if (tid < 128) {
        int p4[4] = {0, 0, 0, 0};
        int q = qb * 128 + tid;
#pragma unroll
        for (int slot = 0; slot < 8; slot++) {
            float bsc = INF; int bidx = 0x7fffffff, bg = 0;
#pragma unroll
            for (int g = 0; g < 4; g++) {
                if (p4[g] < 5) {
                    float s = ms[(tid * 4 + g) * 5 + p4[g]];
                    int i = mi[(tid * 4 + g) * 5 + p4[g]];
                    if (s < bsc || (s == bsc && i < bidx)) { bsc = s; bidx = i; bg = g; }
                }
            }
            g_p8i[q * 32 + ns * 8 + slot] = bidx;
            p4[bg]++;
        }
    }
}

// ---------------- kernel B3D: exact rescore + choice + pos_sim --------------
__global__ void kB3D(const float* __restrict__ bs) {
    __shared__ float qr[8][32];
    int tid = threadIdx.x, wid = tid >> 5, lane = tid & 31;
    int q = blockIdx.x * 8 + wid;
    qr[wid][lane] = bs[(size_t)q * SS + lane];
    __syncwarp();
    int j = g_p8i[q * 32 + lane];
    const float4* cp4 = (const float4*)(bs + (size_t)j * SS);
    const float4* qp4 = (const float4*)qr[wid];
    float dot = 0.0f;
#pragma unroll
    for (int k = 0; k < 8; k++) {
        float4 cv = cp4[k], qv = qp4[k];
        dot += qv.x * cv.x + qv.y * cv.y + qv.z * cv.z + qv.w * cv.w;
    }
    float s = g_bsq[j] - 2.0f * dot;
    int id = j;
    const float INF = __int_as_float(0x7f800000);
    int c = jax_choice5((unsigned)q);
    int chosen = 0;
#pragma unroll
    for (int slot = 0; slot < 5; slot++) {
        float msv = s; int miv = id;
#pragma unroll
        for (int o = 16; o > 0; o >>= 1) {
            float os = __shfl_xor_sync(0xffffffffu, msv, o);
            int oi = __shfl_xor_sync(0xffffffffu, miv, o);
            if (os < msv || (os == msv && oi < miv)) { msv = os; miv = oi; }
        }
        if (slot == c) chosen = miv;
        if (id == miv) s = INF;
    }
    chosen = __shfl_sync(0xffffffffu, chosen, 0);
    uint4 ur = ((const uint4*)(g_znb + (size_t)q * DD))[lane];
    uint4 up = ((const uint4*)(g_znb + (size_t)chosen * DD))[lane];
    const __nv_bfloat162* br = (const __nv_bfloat162*)&ur;
    const __nv_bfloat162* bp = (const __nv_bfloat162*)&up;
    float acc = 0.0f;
#pragma unroll
    for (int e = 0; e < 4; e++) {
        float2 fr = __bfloat1622float2(br[e]);
        float2 fp = __bfloat1622float2(bp[e]);
        acc += fr.x * fp.x + fr.y * fp.y;
    }
    acc = warpsum(acc);
    if (lane == 0) g_possim[q] = acc;
}

// ---------------- kernel C: 128x64 tile HMMA, 3 CTAs/SM ---------------------
// 4160 blocks x 256 thr (4x2 warps, 32x32 warp tile). K=256 in 4 chunks of 64,
// cp.async double-buffered. Epilogue specialized: off-diag fast / diag weighted.
#define KC_AS(s) ((s) * 24576)
#define KC_BSo(s) ((s) * 24576 + 16384)
#define KC_CA   49152
#define KC_SD   49664
#define KC_CB   50176
#define KC_RS   50432
#define KC_CS   50944
#define KC_RED  51200
#define KC_SMEM 51328

__device__ __forceinline__ void kc_load(int bi, int bj, int chunk, int stage,
                                        uint32_t sb, int tid) {
#pragma unroll
    for (int i = 0; i < 4; i++) {
        int f = tid + i * 256;
        int row = f >> 3, u = f & 7;
        cpasync16(sb + KC_AS(stage) + row * 128 + ((u ^ (row & 7)) << 4),
                  g_znb + (size_t)(bi * 128 + row) * DD + chunk * 64 + u * 8);
    }
#pragma unroll
    for (int i = 0; i < 2; i++) {
        int f = tid + i * 256;
        int row = f >> 3, u = f & 7;
        cpasync16(sb + KC_BSo(stage) + row * 128 + ((u ^ (row & 7)) << 4),
                  g_znb + (size_t)(bj * 64 + row) * DD + chunk * 64 + u * 8);
    }
}

__global__ void __launch_bounds__(256, 3) kC() {
    extern __shared__ char smem[];
    const int tid = threadIdx.x, wid = tid >> 5, lane = tid & 31;
    const int warp_m = wid >> 1, warp_n = wid & 1;
    const uint32_t sb = smem_u32(smem);

    // closed-form block -> (bi, bj): cum(bi) = 129*bi - bi^2; bj in [2bi,128)
    int t = blockIdx.x;
    int bi = (int)(0.5f * (129.0f - sqrtf(fmaxf(16641.0f - 4.0f * (float)t, 0.0f))));
    while (bi > 0 && 129 * bi - bi * bi > t) bi--;
    while (129 * (bi + 1) - (bi + 1) * (bi + 1) <= t) bi++;
    const int bj = 2 * bi + (t - (129 * bi - bi * bi));
    const bool diagblk = (bj >> 1) == bi;   // bj == 2bi or 2bi+1

    float* ca = (float*)(smem + KC_CA);
    float* sdg = (float*)(smem + KC_SD);
    float* cb = (float*)(smem + KC_CB);
    float* rsum = (float*)(smem + KC_RS);
    float* csum = (float*)(smem + KC_CS);
    float* red = (float*)(smem + KC_RED);

    kc_load(bi, bj, 0, 0, sb, tid); CP_COMMIT();
    kc_load(bi, bj, 1, 1, sb, tid); CP_COMMIT();

    if (tid < 128) {
        rsum[tid] = 0.0f;
        ca[tid] = g_cexp[bi * 128 + tid];
        sdg[tid] = g_sdiag[bi * 128 + tid];
    }
    if (tid < 64) {
        csum[tid] = 0.0f;
        cb[tid] = g_cexp[bj * 64 + tid];
    }

    const int rA = lane & 15, chA = lane >> 4;
    const int rB = ((lane >> 4) << 3) + (lane & 7), chB = (lane >> 3) & 1;
    uint32_t aoff[2], boff[2];
    int ax[2], bx[2];
#pragma unroll
    for (int mi = 0; mi < 2; mi++) {
        int row = warp_m * 32 + mi * 16 + rA;
        aoff[mi] = row * 128; ax[mi] = row & 7;
    }
#pragma unroll
    for (int nb = 0; nb < 2; nb++) {
        int row = warp_n * 32 + nb * 16 + rB;
        boff[nb] = row * 128; bx[nb] = row & 7;
    }

    float acc[2][4][4] = {};
#pragma unroll
    for (int kc = 0; kc < 4; kc++) {
        if (kc < 3) { CP_WAIT1(); } else { CP_WAIT0(); }
        __syncthreads();
        uint32_t SA = sb + KC_AS(kc & 1), SB = sb + KC_BSo(kc & 1);
#pragma unroll
        for (int ks = 0; ks < 4; ks++) {
            uint32_t af[2][4], bf[2][4];
#pragma unroll
            for (int mi = 0; mi < 2; mi++)
                ldsm4(af[mi][0], af[mi][1], af[mi][2], af[mi][3],
                      SA + aoff[mi] + (((2 * ks + chA) ^ ax[mi]) << 4));
#pragma unroll
            for (int nb = 0; nb < 2; nb++)
                ldsm4(bf[nb][0], bf[nb][1], bf[nb][2], bf[nb][3],
                      SB + boff[nb] + (((2 * ks + chB) ^ bx[nb]) << 4));
#pragma unroll
            for (int mi = 0; mi < 2; mi++)
#pragma unroll
                for (int ni = 0; ni < 4; ni++)
                    hmma(acc[mi][ni], af[mi], &bf[ni >> 1][(ni & 1) * 2]);
        }
        __syncthreads();
        if (kc < 2) { kc_load(bi, bj, kc + 2, kc & 1, sb, tid); CP_COMMIT(); }
    }

    const int qrow = lane >> 2, qcol = (lane & 3) * 2;
    float usum = 0.0f;
    float rowacc[2][2] = {};
    float colacc[4][2] = {};
    if (!diagblk) {
#pragma unroll
        for (int mi = 0; mi < 2; mi++) {
#pragma unroll
            for (int hh = 0; hh < 2; hh++) {
                int lr = warp_m * 32 + mi * 16 + hh * 8 + qrow;
                float cav = ca[lr];
#pragma unroll
                for (int ni = 0; ni < 4; ni++) {
#pragma unroll
                    for (int e = 0; e < 2; e++) {
                        int lc = warp_n * 32 + ni * 8 + qcol + e;
                        float s = acc[mi][ni][hh * 2 + e];
                        float e2 = __expf(2.0f * s);
                        float e4 = e2 * e2;
                        float e10 = e4 * e4 * e2;
                        rowacc[mi][hh] += e10;
                        colacc[ni][e] += e10;
                        usum += 2.0f * fminf(cav * cb[lc] * e4, 1.0f);
                    }
                }
            }
        }
    } else {
        const int growb = bi * 128, gcolb = bj * 64;
#pragma unroll
        for (int mi = 0; mi < 2; mi++) {
#pragma unroll
            for (int hh = 0; hh < 2; hh++) {
                int lr = warp_m * 32 + mi * 16 + hh * 8 + qrow;
                int grow = growb + lr;
                float cav = ca[lr];
                float sdv = sdg[lr];
#pragma unroll
                for (int ni = 0; ni < 4; ni++) {
#pragma unroll
                    for (int e = 0; e < 2; e++) {
                        int lc = warp_n * 32 + ni * 8 + qcol + e;
                        int gcol = gcolb + lc;
                        float s = acc[mi][ni][hh * 2 + e];
                        if (grow == gcol) s = sdv;
                        float w  = (grow <= gcol) ? 1.0f : 0.0f;
                        float wc = (grow <  gcol) ? 1.0f : 0.0f;
                        float e2 = __expf(2.0f * s);
                        float e4 = e2 * e2;
                        float e10 = e4 * e4 * e2;
                        rowacc[mi][hh] += w * e10;
                        colacc[ni][e] += wc * e10;
                        usum += (w + wc) * fminf(cav * cb[lc] * e4, 1.0f);
                    }
                }
            }
        }
    }
#pragma unroll
    for (int mi = 0; mi < 2; mi++)
#pragma unroll
        for (int hh = 0; hh < 2; hh++) {
            float v = rowacc[mi][hh];
            v += __shfl_xor_sync(0xffffffffu, v, 1);
            v += __shfl_xor_sync(0xffffffffu, v, 2);
            if ((lane & 3) == 0)
                atomicAdd(&rsum[warp_m * 32 + mi * 16 + hh * 8 + qrow], v);
        }
#pragma unroll
    for (int ni = 0; ni < 4; ni++)
#pragma unroll
        for (int e = 0; e < 2; e++) {
            float v = colacc[ni][e];
            v += __shfl_xor_sync(0xffffffffu, v, 4);
            v += __shfl_xor_sync(0xffffffffu, v, 8);
            v += __shfl_xor_sync(0xffffffffu, v, 16);
            if (lane < 4)
                atomicAdd(&csum[warp_n * 32 + ni * 8 + qcol + e], v);
        }
    usum = warpsum(usum);
    if (lane == 0) red[wid] = usum;
    __syncthreads();
    if (tid == 0) {
        float tt = 0.0f;
#pragma unroll
        for (int w = 0; w < 8; w++) tt += red[w];
        atomicAdd(&g_unif, tt);
    }
    if (tid < 128) atomicAdd(&g_denom[bi * 128 + tid], rsum[tid]);
    if (tid < 64)  atomicAdd(&g_denom[bj * 64 + tid], csum[tid]);
}

// ---------------- kernel E: final scalar (1024 thr, fast log) ---------------
__global__ void kE(float* __restrict__ out) {
    __shared__ float red[1024];
    int tid = threadIdx.x;
    float acc = 0.0f;
#pragma unroll
    for (int i = tid; i < BN; i += 1024)
        acc += __logf(g_denom[i] + 1e-8f) - g_possim[i] * 10.0f;
    red[tid] = acc;
    __syncthreads();
#pragma unroll
    for (int o = 512; o > 0; o >>= 1) {
        if (tid < o) red[tid] += red[tid + o];
        __syncthreads();
    }
    if (tid == 0) {
        float linfo = red[0] / 8192.0f;
        float lunif = __logf(g_unif * (1.0f / (8192.0f * 8192.0f)) + 1e-8f);
        out[0] = linfo + 0.1f * lunif;
    }
}

extern "C" void kernel_launch(void* const* d_in, const int* in_sizes, int n_in,
                              void* d_out, int out_size) {
    const float* z  = (const float*)d_in[0];
    const float* bs = (const float*)d_in[1];
    float* out = (float*)d_out;
    cudaFuncSetAttribute(kBg, cudaFuncAttributeMaxDynamicSharedMemorySize, KB_SMEM);
    cudaFuncSetAttribute(kC, cudaFuncAttributeMaxDynamicSharedMemorySize, KC_SMEM);

    // fork-join: binding chain (kBg->kB3D) runs concurrently with kC.
    cudaStream_t s1;
    cudaEvent_t eF, eJ;
    cudaStreamCreateWithFlags(&s1, cudaStreamNonBlocking);
    cudaEventCreateWithFlags(&eF, cudaEventDisableTiming);
    cudaEventCreateWithFlags(&eJ, cudaEventDisableTiming);

    kA<<<1024, 256>>>(z, bs);
    cudaEventRecord(eF, 0);
    cudaStreamWaitEvent(s1, eF, 0);

    kBg<<<dim3(64, 4), 256, KB_SMEM, s1>>>();
    kB3D<<<1024, 256, 0, s1>>>(bs);
    cudaEventRecord(eJ, s1);

    kC<<<4160, 256, KC_SMEM>>>();

    cudaStreamWaitEvent(0, eJ, 0);
    kE<<<1, 1024>>>(out);
    // streams/events intentionally not destroyed (capture-involved objects).
}

// round 14
// speedup vs baseline: 1.3159x; 1.0040x over previous
#include <cuda_runtime.h>
#include <cuda_bf16.h>
#include <math.h>
#include <stdint.h>

#define BN 8192
#define DD 256
#define SS 32

// ---------------- device scratch ----------------
__device__ __nv_bfloat16 g_znb[BN * DD]; // normalized z, bf16
__device__ __nv_bfloat16 g_qp[BN * 48];  // query pack  [b | 1 1 | 0...]
__device__ __nv_bfloat16 g_cp[BN * 48];  // cand pack   [b | hi lo | 0...], hi/lo of -||b||^2/2
__device__ float g_cexp[BN];    // exp(-2*||zn_i||^2)
__device__ float g_sdiag[BN];   // ||zn_i||^2 fp32 (exact diagonal sim)
__device__ float g_bsq[BN];     // ||binding_i||^2
__device__ float g_denom[BN];   // per-row sum exp(sim/tau)
__device__ float g_possim[BN];  // sim[i, pos[i]]
__device__ float g_unif;        // sum over all pairs exp(-2*d2)
__device__ int   g_p8i[BN * 32]; // per-(query,nsplit) approx top-8 indices

__device__ __forceinline__ float warpsum(float v) {
#pragma unroll
    for (int o = 16; o > 0; o >>= 1) v += __shfl_down_sync(0xffffffffu, v, o);
    return v;
}
__device__ __forceinline__ uint32_t smem_u32(const void* p) {
    uint32_t a;
    asm("{ .reg .u64 t; cvta.to.shared.u64 t, %1; cvt.u32.u64 %0, t; }" : "=r"(a) : "l"(p));
    return a;
}
__device__ __forceinline__ void ldsm4(uint32_t& r0, uint32_t& r1, uint32_t& r2, uint32_t& r3, uint32_t a) {
    asm volatile("ldmatrix.sync.aligned.m8n8.x4.shared.b16 {%0,%1,%2,%3}, [%4];"
                 : "=r"(r0), "=r"(r1), "=r"(r2), "=r"(r3) : "r"(a));
}
__device__ __forceinline__ void hmma(float* c, const uint32_t* a, const uint32_t* b) {
    asm volatile(
        "mma.sync.aligned.m16n8k16.row.col.f32.bf16.bf16.f32 "
        "{%0,%1,%2,%3}, {%4,%5,%6,%7}, {%8,%9}, {%0,%1,%2,%3};"
        : "+f"(c[0]), "+f"(c[1]), "+f"(c[2]), "+f"(c[3])
        : "r"(a[0]), "r"(a[1]), "r"(a[2]), "r"(a[3]), "r"(b[0]), "r"(b[1]));
}
__device__ __forceinline__ void cpasync16(uint32_t dst, const void* src) {
    asm volatile("cp.async.ca.shared.global [%0], [%1], 16;"
                 :: "r"(dst), "l"(__cvta_generic_to_global(src)) : "memory");
}
#define CP_COMMIT() asm volatile("cp.async.commit_group;" ::: "memory")
#define CP_WAIT1()  asm volatile("cp.async.wait_group 1;" ::: "memory")
#define CP_WAIT0()  asm volatile("cp.async.wait_group 0;" ::: "memory")

// sorted-5 insert keeping LARGEST (descending); strict > keeps lower index on ties
__device__ __forceinline__ void ins5max(float sc, int j, float* s, int* id) {
    if (sc > s[4]) {
        if (sc > s[2]) {
            s[4] = s[3]; id[4] = id[3]; s[3] = s[2]; id[3] = id[2];
            if (sc > s[1]) {
                s[2] = s[1]; id[2] = id[1];
                if (sc > s[0]) { s[1] = s[0]; id[1] = id[0]; s[0] = sc; id[0] = j; }
                else           { s[1] = sc; id[1] = j; }
            } else             { s[2] = sc; id[2] = j; }
        } else {
            if (sc > s[3]) { s[4] = s[3]; id[4] = id[3]; s[3] = sc; id[3] = j; }
            else           { s[4] = sc; id[4] = j; }
        }
    }
}

// ---------------- threefry2x32 (exact JAX, partitionable) ----------------
__device__ __forceinline__ void tf2x32(unsigned k0, unsigned k1,
                                       unsigned x0, unsigned x1,
                                       unsigned& o0, unsigned& o1) {
    unsigned ks0 = k0, ks1 = k1, ks2 = k0 ^ k1 ^ 0x1BD11BDAu;
    x0 += ks0; x1 += ks1;
#define TFR(r) { x0 += x1; x1 = (x1 << r) | (x1 >> (32 - r)); x1 ^= x0; }
    TFR(13) TFR(15) TFR(26) TFR(6)   x0 += ks1; x1 += ks2 + 1u;
    TFR(17) TFR(29) TFR(16) TFR(24)  x0 += ks2; x1 += ks0 + 2u;
    TFR(13) TFR(15) TFR(26) TFR(6)   x0 += ks0; x1 += ks1 + 3u;
    TFR(17) TFR(29) TFR(16) TFR(24)  x0 += ks1; x1 += ks2 + 4u;
    TFR(13) TFR(15) TFR(26) TFR(6)   x0 += ks2; x1 += ks0 + 5u;
#undef TFR
    o0 = x0; o1 = x1;
}
__device__ __forceinline__ int jax_choice5(unsigned i) {
    unsigned a, b, k1a, k1b, k2a, k2b;
    tf2x32(0u, 42u, 0u, 0u, k1a, k1b);
    tf2x32(0u, 42u, 0u, 1u, k2a, k2b);
    tf2x32(k1a, k1b, 0u, i, a, b); unsigned h = a ^ b;
    tf2x32(k2a, k2b, 0u, i, a, b); unsigned l = a ^ b;
    return (int)(((h % 5u) + (l % 5u)) % 5u);
}

// ---------------- kernel A: normalize -> bf16, norms, packs -----------------
__global__ void kA(const float* __restrict__ z, const float* __restrict__ bs) {
    int w = threadIdx.x >> 5, lane = threadIdx.x & 31;
    int r = blockIdx.x * 8 + w;
    const float4* zr = (const float4*)(z + (size_t)r * DD);
    float4 a = zr[2 * lane];
    float4 b = zr[2 * lane + 1];
    float ss = a.x*a.x + a.y*a.y + a.z*a.z + a.w*a.w
             + b.x*b.x + b.y*b.y + b.z*b.z + b.w*b.w;
    ss = warpsum(ss);
    ss = __shfl_sync(0xffffffffu, ss, 0);
    float inv = 1.0f / sqrtf(ss);
    __nv_bfloat162 pk[4];
    pk[0] = __floats2bfloat162_rn(a.x * inv, a.y * inv);
    pk[1] = __floats2bfloat162_rn(a.z * inv, a.w * inv);
    pk[2] = __floats2bfloat162_rn(b.x * inv, b.y * inv);
    pk[3] = __floats2bfloat162_rn(b.z * inv, b.w * inv);
    ((uint4*)(g_znb + (size_t)r * DD))[lane] = *(uint4*)pk;

    float bv = bs[(size_t)r * SS + lane];
    __nv_bfloat16 hv = __float2bfloat16_rn(bv);
    g_qp[(size_t)r * 48 + lane] = hv;
    g_cp[(size_t)r * 48 + lane] = hv;
    float bq = warpsum(bv * bv);
    bq = __shfl_sync(0xffffffffu, bq, 0);
    if (lane < 16) {
        __nv_bfloat16 zero = __float2bfloat16_rn(0.0f);
        __nv_bfloat16 qv = zero, cv = zero;
        if (lane < 2) qv = __float2bfloat16_rn(1.0f);
        float nb2 = -0.5f * bq;
        __nv_bfloat16 hi = __float2bfloat16_rn(nb2);
        if (lane == 0) cv = hi;
        if (lane == 1) cv = __float2bfloat16_rn(nb2 - __bfloat162float(hi));
        g_qp[(size_t)r * 48 + 32 + lane] = qv;
        g_cp[(size_t)r * 48 + 32 + lane] = cv;
    }
    if (lane == 0) {
        float s2 = ss * inv * inv;
        g_cexp[r] = __expf(-2.0f * s2);
        g_sdiag[r] = s2;
        g_bsq[r] = bq;
        g_denom[r] = 0.0f;
    }
    if (blockIdx.x == 0 && threadIdx.x == 0) g_unif = 0.0f;
}

// ---------------- kernel Bg: approx top-8 per split (score in the GEMM) -----
// K=48 pack: acc = q.c - ||c||^2/2; rank DESCENDING == d^2 ascending.
#define BG_A     0
#define BG_S(s)  (16384 + (s) * 16384)
#define BG_MS    0
#define BG_MI    16384
#define KB_SMEM  49152

__device__ __forceinline__ void bg_load(int chunk, int stage, int ns, uint32_t sb, int tid) {
    int j0 = ns * 2048 + chunk * 128;
#pragma unroll
    for (int i = 0; i < 3; i++) {
        int f = tid + i * 256;
        int row = f & 127, u = f >> 7;
        cpasync16(sb + BG_S(stage) + row * 128 + ((u ^ (row & 7)) << 4),
                  g_cp + (size_t)(j0 + row) * 48 + u * 8);
    }
}

__global__ void __launch_bounds__(256, 3) kBg() {
    extern __shared__ char smem[];
    const int qb = blockIdx.x, ns = blockIdx.y;
    const int tid = threadIdx.x, wid = tid >> 5, lane = tid & 31;
    const uint32_t sb = smem_u32(smem);

    // A tile (queries): 128 rows x 6 chunks
#pragma unroll
    for (int i = 0; i < 3; i++) {
        int f = tid + i * 256;
        int row = f & 127, u = f >> 7;
        uint4 v = *(const uint4*)(g_qp + (size_t)(qb * 128 + row) * 48 + u * 8);
        *(uint4*)(smem + BG_A + row * 128 + ((u ^ (row & 7)) << 4)) = v;
    }
    bg_load(0, 0, ns, sb, tid); CP_COMMIT();
    bg_load(1, 1, ns, sb, tid); CP_COMMIT();
    __syncthreads();

    const int rA = lane & 15, chA = lane >> 4;
    const int arow = wid * 16 + rA;
    uint32_t af[3][4];
#pragma unroll
    for (int ks = 0; ks < 3; ks++)
        ldsm4(af[ks][0], af[ks][1], af[ks][2], af[ks][3],
              sb + BG_A + arow * 128 + (((2 * ks + chA) ^ (arow & 7)) << 4));

    const int qrow = lane >> 2, qcol = lane & 3;
    const float NINF = __int_as_float(0xff800000);
    float ts0[5], ts1[5]; int ti0[5], ti1[5];
#pragma unroll
    for (int k = 0; k < 5; k++) {
        ts0[k] = NINF; ts1[k] = NINF; ti0[k] = 0x7fffffff; ti1[k] = 0x7fffffff;
    }
    const int rB = ((lane >> 4) << 3) + (lane & 7), chB = (lane >> 3) & 1;

    for (int it = 0; it < 16; it++) {
        CP_WAIT1();
        __syncthreads();
        uint32_t SB = sb + BG_S(it & 1);
        int j0 = ns * 2048 + it * 128;
#pragma unroll
        for (int p = 0; p < 8; p++) {
            int brow = p * 16 + rB;
            uint32_t ba = SB + brow * 128;
            int bx = brow & 7;
            float acc[2][4] = {};
#pragma unroll
            for (int ks = 0; ks < 3; ks++) {
                uint32_t bk[4];
                ldsm4(bk[0], bk[1], bk[2], bk[3], ba + (((2 * ks + chB) ^ bx) << 4));
                hmma(acc[0], af[ks], &bk[0]);
                hmma(acc[1], af[ks], &bk[2]);
            }
#pragma unroll
            for (int n2 = 0; n2 < 2; n2++) {
#pragma unroll
                for (int e = 0; e < 2; e++) {
                    int j = j0 + p * 16 + n2 * 8 + qcol * 2 + e;
                    ins5max(acc[n2][e], j, ts0, ti0);
                    ins5max(acc[n2][2 + e], j, ts1, ti1);
                }
            }
        }
        __syncthreads();
        if (it < 14) bg_load(it + 2, it & 1, ns, sb, tid);
        CP_COMMIT();
    }
    CP_WAIT0();
    __syncthreads();

    float* ms = (float*)(smem + BG_MS);
    int*   mi = (int*)(smem + BG_MI);
    {
        int r0 = wid * 16 + qrow, r1 = r0 + 8;
#pragma unroll
        for (int k = 0; k < 5; k++) {
            ms[(r0 * 4 + qcol) * 5 + k] = ts0[k]; mi[(r0 * 4 + qcol) * 5 + k] = ti0[k];
            ms[(r1 * 4 + qcol) * 5 + k] = ts1[k]; mi[(r1 * 4 + qcol) * 5 + k] = ti1[k];
        }
    }
    __syncthreads();
    if (tid < 128) {
        int p4[4] = {0, 0, 0, 0};
        int q = qb * 128 + tid;
#pragma unroll
        for (int slot = 0; slot < 8; slot++) {
            float bsc = NINF; int bidx = 0x7fffffff, bg = 0;
#pragma unroll
            for (int g = 0; g < 4; g++) {
                if (p4[g] < 5) {
                    float s = ms[(tid * 4 + g) * 5 + p4[g]];
                    int i = mi[(tid * 4 + g) * 5 + p4[g]];
                    if (s > bsc || (s == bsc && i < bidx)) { bsc = s; bidx = i; bg = g; }
                }
            }
            g_p8i[q * 32 + ns * 8 + slot] = bidx;
            p4[bg]++;
        }
    }
}

// ---------------- kernel B3D: exact rescore (self-excluded) + choice + pos_sim
__global__ void kB3D(const float* __restrict__ bs) {
    __shared__ float qr[8][32];
    int tid = threadIdx.x, wid = tid >> 5, lane = tid & 31;
    int q = blockIdx.x * 8 + wid;
    qr[wid][lane] = bs[(size_t)q * SS + lane];
    __syncwarp();
    int j = g_p8i[q * 32 + lane];
    const float4* cp4 = (const float4*)(bs + (size_t)j * SS);
    const float4* qp4 = (const float4*)qr[wid];
    float dot = 0.0f;
#pragma unroll
    for (int k = 0; k < 8; k++) {
        float4 cv = cp4[k], qv = qp4[k];
        dot += qv.x * cv.x + qv.y * cv.y + qv.z * cv.z + qv.w * cv.w;
    }
    const float INF = __int_as_float(0x7f800000);
    float s = g_bsq[j] - 2.0f * dot;
    if (j == q) s = INF;                   // self-exclusion (approx pass keeps self)
    int id = j;
    int c = jax_choice5((unsigned)q);
    int chosen = 0;
#pragma unroll
    for (int slot = 0; slot < 5; slot++) {
        float msv = s; int miv = id;
#pragma unroll
        for (int o = 16; o > 0; o >>= 1) {
            float os = __shfl_xor_sync(0xffffffffu, msv, o);
            int oi = __shfl_xor_sync(0xffffffffu, miv, o);
            if (os < msv || (os == msv && oi < miv)) { msv = os; miv = oi; }
        }
        if (slot == c) chosen = miv;
        if (id == miv) s = INF;
    }
    chosen = __shfl_sync(0xffffffffu, chosen, 0);
    uint4 ur = ((const uint4*)(g_znb + (size_t)q * DD))[lane];
    uint4 up = ((const uint4*)(g_znb + (size_t)chosen * DD))[lane];
    const __nv_bfloat162* br = (const __nv_bfloat162*)&ur;
    const __nv_bfloat162* bp = (const __nv_bfloat162*)&up;
    float acc = 0.0f;
#pragma unroll
    for (int e = 0; e < 4; e++) {
        float2 fr = __bfloat1622float2(br[e]);
        float2 fp = __bfloat1622float2(bp[e]);
        acc += fr.x * fp.x + fr.y * fp.y;
    }
    acc = warpsum(acc);
    if (lane == 0) g_possim[q] = acc;
}

// ---------------- kernel C: 128x64 tile HMMA, 3 CTAs/SM ---------------------
#define KC_AS(s) ((s) * 24576)
#define KC_BSo(s) ((s) * 24576 + 16384)
#define KC_CA   49152
#define KC_SD   49664
#define KC_CB   50176
#define KC_RS   50432
#define KC_CS   50944
#define KC_RED  51200
#define KC_SMEM 51328

__device__ __forceinline__ void kc_load(int bi, int bj, int chunk, int stage,
                                        uint32_t sb, int tid) {
#pragma unroll
    for (int i = 0; i < 4; i++) {
        int f = tid + i * 256;
        int row = f >> 3, u = f & 7;
        cpasync16(sb + KC_AS(stage) + row * 128 + ((u ^ (row & 7)) << 4),
                  g_znb + (size_t)(bi * 128 + row) * DD + chunk * 64 + u * 8);
    }
#pragma unroll
    for (int i = 0; i < 2; i++) {
        int f = tid + i * 256;
        int row = f >> 3, u = f & 7;
        cpasync16(sb + KC_BSo(stage) + row * 128 + ((u ^ (row & 7)) << 4),
                  g_znb + (size_t)(bj * 64 + row) * DD + chunk * 64 + u * 8);
    }
}

__global__ void __launch_bounds__(256, 3) kC() {
    extern __shared__ char smem[];
    const int tid = threadIdx.x, wid = tid >> 5, lane = tid & 31;
    const int warp_m = wid >> 1, warp_n = wid & 1;
    const uint32_t sb = smem_u32(smem);

    int t = blockIdx.x;
    int bi = (int)(0.5f * (129.0f - sqrtf(fmaxf(16641.0f - 4.0f * (float)t, 0.0f))));
    while (bi > 0 && 129 * bi - bi * bi > t) bi--;
    while (129 * (bi + 1) - (bi + 1) * (bi + 1) <= t) bi++;
    const int bj = 2 * bi + (t - (129 * bi - bi * bi));
    const bool diagblk = (bj >> 1) == bi;

    float* ca = (float*)(smem + KC_CA);
    float* sdg = (float*)(smem + KC_SD);
    float* cb = (float*)(smem + KC_CB);
    float* rsum = (float*)(smem + KC_RS);
    float* csum = (float*)(smem + KC_CS);
    float* red = (float*)(smem + KC_RED);

    kc_load(bi, bj, 0, 0, sb, tid); CP_COMMIT();
    kc_load(bi, bj, 1, 1, sb, tid); CP_COMMIT();

    if (tid < 128) {
        rsum[tid] = 0.0f;
        ca[tid] = g_cexp[bi * 128 + tid];
        sdg[tid] = g_sdiag[bi * 128 + tid];
    }
    if (tid < 64) {
        csum[tid] = 0.0f;
        cb[tid] = g_cexp[bj * 64 + tid];
    }

    const int rA = lane & 15, chA = lane >> 4;
    const int rB = ((lane >> 4) << 3) + (lane & 7), chB = (lane >> 3) & 1;
    uint32_t aoff[2], boff[2];
    int ax[2], bx[2];
#pragma unroll
    for (int mi = 0; mi < 2; mi++) {
        int row = warp_m * 32 + mi * 16 + rA;
        aoff[mi] = row * 128; ax[mi] = row & 7;
    }
#pragma unroll
    for (int nb = 0; nb < 2; nb++) {
        int row = warp_n * 32 + nb * 16 + rB;
        boff[nb] = row * 128; bx[nb] = row & 7;
    }

    float acc[2][4][4] = {};
#pragma unroll
    for (int kc = 0; kc < 4; kc++) {
        if (kc < 3) { CP_WAIT1(); } else { CP_WAIT0(); }
        __syncthreads();
        uint32_t SA = sb + KC_AS(kc & 1), SB = sb + KC_BSo(kc & 1);
#pragma unroll
        for (int ks = 0; ks < 4; ks++) {
            uint32_t af[2][4], bf[2][4];
#pragma unroll
            for (int mi = 0; mi < 2; mi++)
                ldsm4(af[mi][0], af[mi][1], af[mi][2], af[mi][3],
                      SA + aoff[mi] + (((2 * ks + chA) ^ ax[mi]) << 4));
#pragma unroll
            for (int nb = 0; nb < 2; nb++)
                ldsm4(bf[nb][0], bf[nb][1], bf[nb][2], bf[nb][3],
                      SB + boff[nb] + (((2 * ks + chB) ^ bx[nb]) << 4));
#pragma unroll
            for (int mi = 0; mi < 2; mi++)
#pragma unroll
                for (int ni = 0; ni < 4; ni++)
                    hmma(acc[mi][ni], af[mi], &bf[ni >> 1][(ni & 1) * 2]);
        }
        __syncthreads();
        if (kc < 2) { kc_load(bi, bj, kc + 2, kc & 1, sb, tid); CP_COMMIT(); }
    }

    const int qrow = lane >> 2, qcol = (lane & 3) * 2;
    float usum = 0.0f;
    float rowacc[2][2] = {};
    float colacc[4][2] = {};
    if (!diagblk) {
#pragma unroll
        for (int mi = 0; mi < 2; mi++) {
#pragma unroll
            for (int hh = 0; hh < 2; hh++) {
                int lr = warp_m * 32 + mi * 16 + hh * 8 + qrow;
                float cav = ca[lr];
#pragma unroll
                for (int ni = 0; ni < 4; ni++) {
#pragma unroll
                    for (int e = 0; e < 2; e++) {
                        int lc = warp_n * 32 + ni * 8 + qcol + e;
                        float s = acc[mi][ni][hh * 2 + e];
                        float e2 = __expf(2.0f * s);
                        float e4 = e2 * e2;
                        float e10 = e4 * e4 * e2;
                        rowacc[mi][hh] += e10;
                        colacc[ni][e] += e10;
                        usum += 2.0f * fminf(cav * cb[lc] * e4, 1.0f);
                    }
                }
            }
        }
    } else {
        const int growb = bi * 128, gcolb = bj * 64;
#pragma unroll
        for (int mi = 0; mi < 2; mi++) {
#pragma unroll
            for (int hh = 0; hh < 2; hh++) {
                int lr = warp_m * 32 + mi * 16 + hh * 8 + qrow;
                int grow = growb + lr;
                float cav = ca[lr];
                float sdv = sdg[lr];
#pragma unroll
                for (int ni = 0; ni < 4; ni++) {
#pragma unroll
                    for (int e = 0; e < 2; e++) {
                        int lc = warp_n * 32 + ni * 8 + qcol + e;
                        int gcol = gcolb + lc;
                        float s = acc[mi][ni][hh * 2 + e];
                        if (grow == gcol) s = sdv;
                        float w  = (grow <= gcol) ? 1.0f : 0.0f;
                        float wc = (grow <  gcol) ? 1.0f : 0.0f;
                        float e2 = __expf(2.0f * s);
                        float e4 = e2 * e2;
                        float e10 = e4 * e4 * e2;
                        rowacc[mi][hh] += w * e10;
                        colacc[ni][e] += wc * e10;
                        usum += (w + wc) * fminf(cav * cb[lc] * e4, 1.0f);
                    }
                }
            }
        }
    }
#pragma unroll
    for (int mi = 0; mi < 2; mi++)
#pragma unroll
        for (int hh = 0; hh < 2; hh++) {
            float v = rowacc[mi][hh];
            v += __shfl_xor_sync(0xffffffffu, v, 1);
            v += __shfl_xor_sync(0xffffffffu, v, 2);
            if ((lane & 3) == 0)
                atomicAdd(&rsum[warp_m * 32 + mi * 16 + hh * 8 + qrow], v);
        }
#pragma unroll
    for (int ni = 0; ni < 4; ni++)
#pragma unroll
        for (int e = 0; e < 2; e++) {
            float v = colacc[ni][e];
            v += __shfl_xor_sync(0xffffffffu, v, 4);
            v += __shfl_xor_sync(0xffffffffu, v, 8);
            v += __shfl_xor_sync(0xffffffffu, v, 16);
            if (lane < 4)
                atomicAdd(&csum[warp_n * 32 + ni * 8 + qcol + e], v);
        }
    usum = warpsum(usum);
    if (lane == 0) red[wid] = usum;
    __syncthreads();
    if (tid == 0) {
        float tt = 0.0f;
#pragma unroll
        for (int w = 0; w < 8; w++) tt += red[w];
        atomicAdd(&g_unif, tt);
    }
    if (tid < 128) atomicAdd(&g_denom[bi * 128 + tid], rsum[tid]);
    if (tid < 64)  atomicAdd(&g_denom[bj * 64 + tid], csum[tid]);
}

// ---------------- kernel E: final scalar (1024 thr, fast log) ---------------
__global__ void kE(float* __restrict__ out) {
    __shared__ float red[1024];
    int tid = threadIdx.x;
    float acc = 0.0f;
#pragma unroll
    for (int i = tid; i < BN; i += 1024)
        acc += __logf(g_denom[i] + 1e-8f) - g_possim[i] * 10.0f;
    red[tid] = acc;
    __syncthreads();
#pragma unroll
    for (int o = 512; o > 0; o >>= 1) {
        if (tid < o) red[tid] += red[tid + o];
        __syncthreads();
    }
    if (tid == 0) {
        float linfo = red[0] / 8192.0f;
        float lunif = __logf(g_unif * (1.0f / (8192.0f * 8192.0f)) + 1e-8f);
        out[0] = linfo + 0.1f * lunif;
    }
}

extern "C" void kernel_launch(void* const* d_in, const int* in_sizes, int n_in,
                              void* d_out, int out_size) {
    const float* z  = (const float*)d_in[0];
    const float* bs = (const float*)d_in[1];
    float* out = (float*)d_out;
    cudaFuncSetAttribute(kBg, cudaFuncAttributeMaxDynamicSharedMemorySize, KB_SMEM);
    cudaFuncSetAttribute(kC, cudaFuncAttributeMaxDynamicSharedMemorySize, KC_SMEM);

    // fork-join: binding chain (kBg->kB3D) runs concurrently with kC.
    cudaStream_t s1;
    cudaEvent_t eF, eJ;
    cudaStreamCreateWithFlags(&s1, cudaStreamNonBlocking);
    cudaEventCreateWithFlags(&eF, cudaEventDisableTiming);
    cudaEventCreateWithFlags(&eJ, cudaEventDisableTiming);

    kA<<<1024, 256>>>(z, bs);
    cudaEventRecord(eF, 0);
    cudaStreamWaitEvent(s1, eF, 0);

    kBg<<<dim3(64, 4), 256, KB_SMEM, s1>>>();
    kB3D<<<1024, 256, 0, s1>>>(bs);
    cudaEventRecord(eJ, s1);

    kC<<<4160, 256, KC_SMEM>>>();

    cudaStreamWaitEvent(0, eJ, 0);
    kE<<<1, 1024>>>(out);
    // streams/events intentionally not destroyed (capture-involved objects).
}